// round 13
// baseline (speedup 1.0000x reference)
#include <cuda_runtime.h>
#include <cuda_fp16.h>
#include <math.h>
#include <cstdint>

#define D_MODEL 1280
#define NHEADS  16
#define HDIM    80
#define S_MAX   4096

// ---------------- scratch (device globals; no allocation allowed) ----------
__device__ float  g_qkv[S_MAX * 3 * D_MODEL];
__device__ __half g_hh[S_MAX * D_MODEL];                 // hidden fp16
__device__ __half g_attnh[S_MAX * D_MODEL];              // attn out fp16
__device__ __half g_wqkv_h[3 * D_MODEL * D_MODEL];       // (3D, D) K-major fp16
__device__ __half g_wproj_h[D_MODEL * D_MODEL];
// fp16 attention tensors (Q/K hi+lo split, V hi only)
__device__ __half g_qh[NHEADS * S_MAX * HDIM];           // (H,S,80) scaled
__device__ __half g_ql[NHEADS * S_MAX * HDIM];
__device__ __half g_kh[NHEADS * S_MAX * HDIM];
__device__ __half g_kl[NHEADS * S_MAX * HDIM];
__device__ __half g_vh[NHEADS * HDIM * S_MAX];           // (H,80,S) transposed

// ======================= helpers ===========================================
__device__ __forceinline__ uint32_t smem_u32(const void* p) {
    uint32_t a;
    asm("{ .reg .u64 t; cvta.to.shared.u64 t, %1; cvt.u32.u64 %0, t; }" : "=r"(a) : "l"(p));
    return a;
}
__device__ __forceinline__ void cp16(uint32_t dst, const void* src) {
    asm volatile("cp.async.cg.shared.global [%0], [%1], 16;" :: "r"(dst), "l"(src));
}
#define CP_COMMIT() asm volatile("cp.async.commit_group;" ::: "memory")
#define CP_WAIT(n)  asm volatile("cp.async.wait_group %0;" :: "n"(n) : "memory")

__device__ __forceinline__ void mma_f16(float* c, const uint32_t* a, const uint32_t* b) {
    asm volatile(
        "mma.sync.aligned.m16n8k16.row.col.f32.f16.f16.f32 "
        "{%0,%1,%2,%3}, {%4,%5,%6,%7}, {%8,%9}, {%0,%1,%2,%3};"
        : "+f"(c[0]), "+f"(c[1]), "+f"(c[2]), "+f"(c[3])
        : "r"(a[0]), "r"(a[1]), "r"(a[2]), "r"(a[3]), "r"(b[0]), "r"(b[1]));
}
__device__ __forceinline__ void ldsm4(uint32_t* r, uint32_t addr) {
    asm volatile("ldmatrix.sync.aligned.m8n8.x4.shared.b16 {%0,%1,%2,%3}, [%4];"
        : "=r"(r[0]), "=r"(r[1]), "=r"(r[2]), "=r"(r[3]) : "r"(addr));
}
__device__ __forceinline__ uint32_t pack_h2(float lo, float hi) {
    __half2 h = __floats2half2_rn(lo, hi);
    return *reinterpret_cast<uint32_t*>(&h);
}

// ======================= weight transpose -> fp16 ==========================
__global__ void wtrans16(const float* __restrict__ in, __half* __restrict__ oh,
                         int K, int N) {
    __shared__ float tile[32][33];
    const int k0 = blockIdx.y * 32, n0 = blockIdx.x * 32;
    const int tx = threadIdx.x, ty = threadIdx.y;
    #pragma unroll
    for (int i = ty; i < 32; i += 8)
        tile[i][tx] = in[(size_t)(k0 + i) * N + n0 + tx];
    __syncthreads();
    #pragma unroll
    for (int i = ty; i < 32; i += 8)
        oh[(size_t)(n0 + i) * K + k0 + tx] = __float2half_rn(tile[tx][i]);
}

// ======================= fp32 -> fp16 convert ==============================
__global__ void f2h(const float* __restrict__ in, __half* __restrict__ out) {
    const int i = (blockIdx.x * blockDim.x + threadIdx.x) * 4;
    float4 v = *reinterpret_cast<const float4*>(in + i);
    __half2 a = __floats2half2_rn(v.x, v.y);
    __half2 b = __floats2half2_rn(v.z, v.w);
    uint2 pk;
    pk.x = *reinterpret_cast<uint32_t*>(&a);
    pk.y = *reinterpret_cast<uint32_t*>(&b);
    *reinterpret_cast<uint2*>(out + i) = pk;
}

// ======================= plain fp16 GEMM (128x128, BK=64, 2-stage) =========
#define ASTR 72                              // 64 data + 8 pad halves
#define GEMM_STAGE (2 * 128 * ASTR)          // 18432 halves = 36864 B
#define GEMM_SMEM  73728

__global__ __launch_bounds__(256)
void gemm_f16(const __half* __restrict__ A, const __half* __restrict__ B,
              const float* __restrict__ bias, float* __restrict__ C,
              int M, int N, int K)
{
    extern __shared__ __half smh[];
    const int tid  = threadIdx.x;
    const int warp = tid >> 5, lane = tid & 31;
    const int gid  = lane >> 2, t4 = lane & 3;
    const int mrow = lane & 7, msel = lane >> 3;
    const int wm0  = (warp & 3) * 32;
    const int wn0  = (warp >> 2) * 64;
    const int bx = blockIdx.x, by = blockIdx.y;

    const __half* Ab = A + (size_t)by * 128 * K;
    const __half* Bb = B + (size_t)bx * 128 * K;
    const int NS = K / 64;
    const uint32_t sb = smem_u32(smh);

    auto load_stage = [&](int s, int ks) {
        #pragma unroll
        for (int i = 0; i < 8; i++) {
            const int id  = tid + i * 256;
            const int isB = id >= 1024;
            const int id2 = isB ? id - 1024 : id;
            const int row = id2 >> 3;
            const int c8  = (id2 & 7) * 8;
            const __half* src = (isB ? Bb : Ab) + (size_t)row * K + ks * 64 + c8;
            const uint32_t dst = sb +
                (uint32_t)(s * GEMM_STAGE + isB * 128 * ASTR + row * ASTR + c8) * 2u;
            cp16(dst, src);
        }
        CP_COMMIT();
    };

    float acc[2][8][4];
    #pragma unroll
    for (int mt = 0; mt < 2; mt++)
        #pragma unroll
        for (int nt = 0; nt < 8; nt++)
            #pragma unroll
            for (int r = 0; r < 4; r++) acc[mt][nt][r] = 0.f;

    load_stage(0, 0);
    for (int ks = 0; ks < NS; ks++) {
        const int s = ks & 1;
        if (ks + 1 < NS) { load_stage(1 - s, ks + 1); CP_WAIT(1); }
        else             { CP_WAIT(0); }
        __syncthreads();

        const uint32_t uA = sb + (uint32_t)(s * GEMM_STAGE) * 2u;
        const uint32_t uB = uA + (uint32_t)(128 * ASTR) * 2u;

        #pragma unroll
        for (int kk = 0; kk < 4; kk++) {
            const int kb = kk * 16;
            uint32_t a0[4], a1[4];
            const uint32_t aoff = (uint32_t)((wm0 + (lane & 15)) * ASTR + kb
                                             + ((lane & 16) ? 8 : 0)) * 2u;
            ldsm4(a0, uA + aoff);
            ldsm4(a1, uA + aoff + (uint32_t)(16 * ASTR) * 2u);
            #pragma unroll
            for (int np = 0; np < 4; np++) {
                const uint32_t boff = (uint32_t)((wn0 + np * 16 + (msel >> 1) * 8 + mrow) * ASTR
                                                 + kb + (msel & 1) * 8) * 2u;
                uint32_t b4[4];
                ldsm4(b4, uB + boff);
                mma_f16(acc[0][2 * np],     a0, b4 + 0);
                mma_f16(acc[0][2 * np + 1], a0, b4 + 2);
                mma_f16(acc[1][2 * np],     a1, b4 + 0);
                mma_f16(acc[1][2 * np + 1], a1, b4 + 2);
            }
        }
        __syncthreads();
    }

    float* Cs = reinterpret_cast<float*>(smh);
    #pragma unroll
    for (int mt = 0; mt < 2; mt++)
        #pragma unroll
        for (int nt = 0; nt < 8; nt++) {
            const int row = wm0 + mt * 16 + gid;
            const int col = wn0 + nt * 8 + t4 * 2;
            Cs[row * 132 + col]           = acc[mt][nt][0];
            Cs[row * 132 + col + 1]       = acc[mt][nt][1];
            Cs[(row + 8) * 132 + col]     = acc[mt][nt][2];
            Cs[(row + 8) * 132 + col + 1] = acc[mt][nt][3];
        }
    __syncthreads();
    #pragma unroll
    for (int it = 0; it < 16; it++) {
        const int id  = tid + it * 256;
        const int row = id >> 5;
        const int c4  = (id & 31) * 4;
        float4 v = *reinterpret_cast<const float4*>(&Cs[row * 132 + c4]);
        const int gc = bx * 128 + c4;
        v.x += bias[gc + 0]; v.y += bias[gc + 1]; v.z += bias[gc + 2]; v.w += bias[gc + 3];
        *reinterpret_cast<float4*>(&C[(size_t)(by * 128 + row) * N + gc]) = v;
    }
}

// ======================= fused prep: RoPE split + V transpose ==============
// block = (64 tokens, 1 head), 256 threads.
__global__ void prep_qkv(const float* __restrict__ qkv,
                         const float* __restrict__ freqs,
                         __half* __restrict__ Qh, __half* __restrict__ Ql,
                         __half* __restrict__ Kh, __half* __restrict__ Kl,
                         __half* __restrict__ Vh, int S)
{
    __shared__ float tile[64][84];
    const int tid = threadIdx.x;
    const int h   = blockIdx.y;
    const int s0  = blockIdx.x * 64;
    const int sl  = tid >> 2;              // token 0..63
    const int dc  = (tid & 3) * 20;        // dim chunk
    const int s   = s0 + sl;
    const float scale = 0.11180339887498949f;   // 1/sqrt(80)

    // ---- V: load into smem tile, then write transposed fp16 ----
    {
        const float* src = qkv + (size_t)s * (3 * D_MODEL) + 2 * D_MODEL + h * HDIM + dc;
        #pragma unroll
        for (int i = 0; i < 5; i++) {
            float4 v = *reinterpret_cast<const float4*>(src + i * 4);
            tile[sl][dc + i * 4 + 0] = v.x;
            tile[sl][dc + i * 4 + 1] = v.y;
            tile[sl][dc + i * 4 + 2] = v.z;
            tile[sl][dc + i * 4 + 3] = v.w;
        }
    }

    // ---- Q/K: rope + hi/lo split (independent of smem) ----
    {
        const float* base = qkv + (size_t)s * (3 * D_MODEL) + h * HDIM;
        const size_t o = ((size_t)h * S + s) * HDIM;
        #pragma unroll
        for (int j = 0; j < 20; j++) {
            const int d  = dc + j;
            const int dd = (d < 40) ? d : d - 40;
            const float f  = freqs[(size_t)s * 40 + dd];
            const float cs = cosf(f), sn = sinf(f);
            const float q1 = base[dd];
            const float q2 = base[dd + 40];
            const float k1 = base[D_MODEL + dd];
            const float k2 = base[D_MODEL + dd + 40];
            float qo = (d < 40) ? (q1 * cs - q2 * sn) : (q1 * sn + q2 * cs);
            const float ko = (d < 40) ? (k1 * cs - k2 * sn) : (k1 * sn + k2 * cs);
            qo *= scale;
            const __half qhi = __float2half_rn(qo);
            Qh[o + d] = qhi;
            Ql[o + d] = __float2half_rn(qo - __half2float(qhi));
            const __half khi = __float2half_rn(ko);
            Kh[o + d] = khi;
            Kl[o + d] = __float2half_rn(ko - __half2float(khi));
        }
    }

    __syncthreads();
    // ---- write V transposed (fp16 hi only) ----
    if (tid < 160) {
        const int d  = tid >> 1;
        const int shh = (tid & 1) * 32;
        const size_t o = ((size_t)(h * HDIM + d)) * S + s0 + shh;
        #pragma unroll
        for (int j = 0; j < 16; j++) {
            __half2 hv = __floats2half2_rn(tile[shh + 2 * j][d], tile[shh + 2 * j + 1][d]);
            *reinterpret_cast<__half2*>(&Vh[o + 2 * j]) = hv;
        }
    }
}

// ======================= fp16-split tensor-core attention ==================
// CTA = (q-tile 256, head), 16 warps x 16 q-rows, KV tile 64, 2-stage cp.async.
// QK^T: 3-MMA hi/lo split. PV: plain fp16 V (1 MMA).
#define QSTR 88
#define VSTR 72
#define ATT_Q  (256 * QSTR)
#define ATT_K  (64 * QSTR)
#define ATT_V  (80 * VSTR)
#define ATC_SMEM ((2 * ATT_Q + 4 * ATT_K + 2 * ATT_V) * 2)   // 158208 B

__global__ __launch_bounds__(512)
void attn_tc(const __half* __restrict__ gQh, const __half* __restrict__ gQl,
             const __half* __restrict__ gKh, const __half* __restrict__ gKl,
             const __half* __restrict__ gVh,
             const int* __restrict__ cu, int n_seg,
             __half* __restrict__ outh, int S)
{
    extern __shared__ __half sh[];
    __half* Qh = sh;
    __half* Ql = Qh + ATT_Q;
    __half* Kh = Ql + ATT_Q;           // [2][ATT_K]
    __half* Kl = Kh + 2 * ATT_K;
    __half* Vh = Kl + 2 * ATT_K;       // [2][ATT_V]

    const uint32_t uQh = smem_u32(Qh), uQl = smem_u32(Ql);
    const uint32_t uKh = smem_u32(Kh), uKl = smem_u32(Kl);
    const uint32_t uVh = smem_u32(Vh);

    const int tid  = threadIdx.x;
    const int warp = tid >> 5, lane = tid & 31;
    const int gid  = lane >> 2, t4 = lane & 3;
    const int mrow = lane & 7, msel = lane >> 3;
    const int wq   = warp * 16;
    const int h    = blockIdx.y;
    const int q0   = blockIdx.x * 256;

    int start = 0, end = S;
    for (int i = 0; i < n_seg; i++) {
        int a = cu[i], b = cu[i + 1];
        if (a <= q0 && q0 < b) { start = a; end = b; }
    }

    // ---- Q load (cp.async) ----
    #pragma unroll
    for (int i = 0; i < 10; i++) {
        const int id  = tid + i * 512;        // 0..5119
        const int isL = id >= 2560;
        const int id2 = isL ? id - 2560 : id;
        const int r   = id2 / 10;
        const int c8  = (id2 % 10) * 8;
        const size_t so = ((size_t)h * S + q0 + r) * HDIM + c8;
        const uint32_t dst = (isL ? uQl : uQh) + (uint32_t)(r * QSTR + c8) * 2u;
        cp16(dst, (isL ? gQl : gQh) + so);
    }

    const int nkt = (end - start + 63) / 64;

    // KV loader: K hi+lo (1280 chunks) + V hi (640 chunks) = 1920
    auto load_kv = [&](int st, int t) {
        const int k0 = start + t * 64;
        #pragma unroll
        for (int i = 0; i < 4; i++) {
            const int id = tid + i * 512;     // 0..2047
            if (id < 1280) {                  // K
                const int isL = id >= 640;
                const int id2 = isL ? id - 640 : id;
                const int r   = id2 / 10;
                const int c8  = (id2 % 10) * 8;
                const size_t so = ((size_t)h * S + k0 + r) * HDIM + c8;
                const uint32_t dst = (isL ? uKl : uKh) +
                    (uint32_t)(st * ATT_K + r * QSTR + c8) * 2u;
                cp16(dst, (isL ? gKl : gKh) + so);
            } else if (id < 1920) {           // V hi
                const int idv = id - 1280;
                const int r   = idv >> 3;
                const int c8  = (idv & 7) * 8;
                const size_t so = ((size_t)(h * HDIM + r)) * S + k0 + c8;
                const uint32_t dst = uVh +
                    (uint32_t)(st * ATT_V + r * VSTR + c8) * 2u;
                cp16(dst, gVh + so);
            }
        }
        CP_COMMIT();
    };

    load_kv(0, 0);

    float acc_o[10][4];
    #pragma unroll
    for (int n = 0; n < 10; n++)
        #pragma unroll
        for (int r = 0; r < 4; r++) acc_o[n][r] = 0.f;
    float m0 = -INFINITY, m1 = -INFINITY, l0 = 0.f, l1 = 0.f;

    for (int t = 0; t < nkt; t++) {
        const int b = t & 1;
        if (t + 1 < nkt) { load_kv(1 - b, t + 1); CP_WAIT(1); }
        else             { CP_WAIT(0); }
        __syncthreads();

        const uint32_t kB = (uint32_t)(b * ATT_K) * 2u;
        const uint32_t vB = (uint32_t)(b * ATT_V) * 2u;

        // ---- QK^T: 5 k16-blocks, 3-MMA hi/lo split ----
        float acc_s[8][4];
        #pragma unroll
        for (int n = 0; n < 8; n++)
            #pragma unroll
            for (int r = 0; r < 4; r++) acc_s[n][r] = 0.f;

        #pragma unroll
        for (int kk = 0; kk < 5; kk++) {
            const int kb = kk * 16;
            uint32_t ah[4], al[4];
            {
                const uint32_t off = (uint32_t)((wq + (lane & 15)) * QSTR + kb
                                                + ((lane & 16) ? 8 : 0)) * 2u;
                ldsm4(ah, uQh + off);
                ldsm4(al, uQl + off);
            }
            #pragma unroll
            for (int np = 0; np < 4; np++) {
                const uint32_t off = (uint32_t)((np * 16 + (msel >> 1) * 8 + mrow) * QSTR
                                                + kb + (msel & 1) * 8) * 2u;
                uint32_t bh4[4], bl4[4];
                ldsm4(bh4, uKh + kB + off);
                ldsm4(bl4, uKl + kB + off);
                mma_f16(acc_s[2 * np],     ah, bh4 + 0);
                mma_f16(acc_s[2 * np],     al, bh4 + 0);
                mma_f16(acc_s[2 * np],     ah, bl4 + 0);
                mma_f16(acc_s[2 * np + 1], ah, bh4 + 2);
                mma_f16(acc_s[2 * np + 1], al, bh4 + 2);
                mma_f16(acc_s[2 * np + 1], ah, bl4 + 2);
            }
        }

        // ---- mask + online softmax ----
        const int k0 = start + t * 64;
        const int nv = end - k0;
        float mt0 = -INFINITY, mt1 = -INFINITY;
        #pragma unroll
        for (int nt = 0; nt < 8; nt++) {
            #pragma unroll
            for (int j = 0; j < 2; j++) {
                const int c = nt * 8 + 2 * t4 + j;
                if (c >= nv) { acc_s[nt][j] = -1e30f; acc_s[nt][2 + j] = -1e30f; }
                mt0 = fmaxf(mt0, acc_s[nt][j]);
                mt1 = fmaxf(mt1, acc_s[nt][2 + j]);
            }
        }
        mt0 = fmaxf(mt0, __shfl_xor_sync(0xffffffffu, mt0, 1));
        mt0 = fmaxf(mt0, __shfl_xor_sync(0xffffffffu, mt0, 2));
        mt1 = fmaxf(mt1, __shfl_xor_sync(0xffffffffu, mt1, 1));
        mt1 = fmaxf(mt1, __shfl_xor_sync(0xffffffffu, mt1, 2));

        const float mn0 = fmaxf(m0, mt0), mn1 = fmaxf(m1, mt1);
        const float al0 = __expf(m0 - mn0), al1 = __expf(m1 - mn1);
        m0 = mn0; m1 = mn1;

        float rs0 = 0.f, rs1 = 0.f;
        #pragma unroll
        for (int nt = 0; nt < 8; nt++) {
            #pragma unroll
            for (int j = 0; j < 2; j++) {
                const float p0 = __expf(acc_s[nt][j]     - m0);
                const float p1 = __expf(acc_s[nt][2 + j] - m1);
                acc_s[nt][j]     = p0;
                acc_s[nt][2 + j] = p1;
                rs0 += p0; rs1 += p1;
            }
        }
        rs0 += __shfl_xor_sync(0xffffffffu, rs0, 1);
        rs0 += __shfl_xor_sync(0xffffffffu, rs0, 2);
        rs1 += __shfl_xor_sync(0xffffffffu, rs1, 1);
        rs1 += __shfl_xor_sync(0xffffffffu, rs1, 2);
        l0 = l0 * al0 + rs0;
        l1 = l1 * al1 + rs1;

        #pragma unroll
        for (int n = 0; n < 10; n++) {
            acc_o[n][0] *= al0; acc_o[n][1] *= al0;
            acc_o[n][2] *= al1; acc_o[n][3] *= al1;
        }

        // ---- pack P into fp16 A-fragments ----
        uint32_t pk[4][4];
        #pragma unroll
        for (int kk = 0; kk < 4; kk++) {
            pk[kk][0] = pack_h2(acc_s[2 * kk][0],     acc_s[2 * kk][1]);
            pk[kk][1] = pack_h2(acc_s[2 * kk][2],     acc_s[2 * kk][3]);
            pk[kk][2] = pack_h2(acc_s[2 * kk + 1][0], acc_s[2 * kk + 1][1]);
            pk[kk][3] = pack_h2(acc_s[2 * kk + 1][2], acc_s[2 * kk + 1][3]);
        }

        // ---- PV: 4 k16-blocks, plain fp16 V ----
        #pragma unroll
        for (int kk = 0; kk < 4; kk++) {
            const int kb = kk * 16;
            #pragma unroll
            for (int vp = 0; vp < 5; vp++) {
                const uint32_t off = (uint32_t)((vp * 16 + (msel >> 1) * 8 + mrow) * VSTR
                                                + kb + (msel & 1) * 8) * 2u;
                uint32_t vh4[4];
                ldsm4(vh4, uVh + vB + off);
                mma_f16(acc_o[2 * vp],     pk[kk], vh4 + 0);
                mma_f16(acc_o[2 * vp + 1], pk[kk], vh4 + 2);
            }
        }
        __syncthreads();
    }

    // ---- epilogue: write fp16 ----
    const float inv0 = 1.f / l0, inv1 = 1.f / l1;
    const int r0 = q0 + wq + gid, r1 = r0 + 8;
    #pragma unroll
    for (int nt = 0; nt < 10; nt++) {
        const int col = h * HDIM + nt * 8 + 2 * t4;
        __half2 v0 = __floats2half2_rn(acc_o[nt][0] * inv0, acc_o[nt][1] * inv0);
        __half2 v1 = __floats2half2_rn(acc_o[nt][2] * inv1, acc_o[nt][3] * inv1);
        *reinterpret_cast<__half2*>(&outh[(size_t)r0 * D_MODEL + col]) = v0;
        *reinterpret_cast<__half2*>(&outh[(size_t)r1 * D_MODEL + col]) = v1;
    }
}

// ======================= launch ============================================
extern "C" void kernel_launch(void* const* d_in, const int* in_sizes, int n_in,
                              void* d_out, int out_size)
{
    const float* hidden = (const float*)d_in[0];
    const int*   cu     = (const int*)  d_in[1];
    const float* rope   = (const float*)d_in[2];
    const float* w_qkv  = (const float*)d_in[3];
    const float* b_qkv  = (const float*)d_in[4];
    const float* w_proj = (const float*)d_in[5];
    const float* b_proj = (const float*)d_in[6];
    float* out = (float*)d_out;

    const int S     = in_sizes[0] / D_MODEL;
    const int n_seg = in_sizes[1] - 1;

    float *qkv_p;
    __half *hh, *attnh, *wqh, *wph, *qh, *ql, *kh, *kl, *vh;
    cudaGetSymbolAddress((void**)&qkv_p, g_qkv);
    cudaGetSymbolAddress((void**)&hh,    g_hh);
    cudaGetSymbolAddress((void**)&attnh, g_attnh);
    cudaGetSymbolAddress((void**)&wqh,   g_wqkv_h);
    cudaGetSymbolAddress((void**)&wph,   g_wproj_h);
    cudaGetSymbolAddress((void**)&qh, g_qh);
    cudaGetSymbolAddress((void**)&ql, g_ql);
    cudaGetSymbolAddress((void**)&kh, g_kh);
    cudaGetSymbolAddress((void**)&kl, g_kl);
    cudaGetSymbolAddress((void**)&vh, g_vh);

    cudaFuncSetAttribute(gemm_f16, cudaFuncAttributeMaxDynamicSharedMemorySize, GEMM_SMEM);
    cudaFuncSetAttribute(attn_tc,  cudaFuncAttributeMaxDynamicSharedMemorySize, ATC_SMEM);

    // 0) weight transpose -> fp16; hidden -> fp16
    {
        dim3 blk(32, 8);
        wtrans16<<<dim3(3 * D_MODEL / 32, D_MODEL / 32), blk>>>(w_qkv, wqh, D_MODEL, 3 * D_MODEL);
        wtrans16<<<dim3(D_MODEL / 32, D_MODEL / 32), blk>>>(w_proj, wph, D_MODEL, D_MODEL);
        f2h<<<(S * D_MODEL) / (256 * 4), 256>>>(hidden, hh);
    }

    // 1) QKV projection (plain fp16, BK=64)
    gemm_f16<<<dim3(3 * D_MODEL / 128, S / 128), 256, GEMM_SMEM>>>(
        hh, wqh, b_qkv, qkv_p, S, 3 * D_MODEL, D_MODEL);

    // 2) fused RoPE split + V transpose
    prep_qkv<<<dim3(S / 64, NHEADS), 256>>>(qkv_p, rope, qh, ql, kh, kl, vh, S);

    // 3) block-diagonal attention
    attn_tc<<<dim3(S / 256, NHEADS), 512, ATC_SMEM>>>(
        qh, ql, kh, kl, vh, cu, n_seg, attnh, S);

    // 4) output projection (plain fp16, BK=64)
    gemm_f16<<<dim3(D_MODEL / 128, S / 128), 256, GEMM_SMEM>>>(
        attnh, wph, b_proj, out, S, D_MODEL, D_MODEL);
}

// round 14
// speedup vs baseline: 1.2852x; 1.2852x over previous
#include <cuda_runtime.h>
#include <cuda_fp16.h>
#include <math.h>
#include <cstdint>

#define D_MODEL 1280
#define NHEADS  16
#define HDIM    80
#define S_MAX   4096

// ---------------- scratch (device globals; no allocation allowed) ----------
__device__ float  g_qkv[S_MAX * 3 * D_MODEL];
__device__ __half g_hh[S_MAX * D_MODEL];                 // hidden fp16
__device__ __half g_attnh[S_MAX * D_MODEL];              // attn out fp16
__device__ __half g_wqkv_h[3 * D_MODEL * D_MODEL];       // (3D, D) K-major fp16
__device__ __half g_wproj_h[D_MODEL * D_MODEL];
// fp16 attention tensors (Q/K hi+lo split, V hi only)
__device__ __half g_qh[NHEADS * S_MAX * HDIM];           // (H,S,80) scaled
__device__ __half g_ql[NHEADS * S_MAX * HDIM];
__device__ __half g_kh[NHEADS * S_MAX * HDIM];
__device__ __half g_kl[NHEADS * S_MAX * HDIM];
__device__ __half g_vh[NHEADS * HDIM * S_MAX];           // (H,80,S) transposed

// ======================= helpers ===========================================
__device__ __forceinline__ uint32_t smem_u32(const void* p) {
    uint32_t a;
    asm("{ .reg .u64 t; cvta.to.shared.u64 t, %1; cvt.u32.u64 %0, t; }" : "=r"(a) : "l"(p));
    return a;
}
__device__ __forceinline__ void cp16(uint32_t dst, const void* src) {
    asm volatile("cp.async.cg.shared.global [%0], [%1], 16;" :: "r"(dst), "l"(src));
}
#define CP_COMMIT() asm volatile("cp.async.commit_group;" ::: "memory")
#define CP_WAIT(n)  asm volatile("cp.async.wait_group %0;" :: "n"(n) : "memory")

__device__ __forceinline__ void mma_f16(float* c, const uint32_t* a, const uint32_t* b) {
    asm volatile(
        "mma.sync.aligned.m16n8k16.row.col.f32.f16.f16.f32 "
        "{%0,%1,%2,%3}, {%4,%5,%6,%7}, {%8,%9}, {%0,%1,%2,%3};"
        : "+f"(c[0]), "+f"(c[1]), "+f"(c[2]), "+f"(c[3])
        : "r"(a[0]), "r"(a[1]), "r"(a[2]), "r"(a[3]), "r"(b[0]), "r"(b[1]));
}
__device__ __forceinline__ void ldsm4(uint32_t* r, uint32_t addr) {
    asm volatile("ldmatrix.sync.aligned.m8n8.x4.shared.b16 {%0,%1,%2,%3}, [%4];"
        : "=r"(r[0]), "=r"(r[1]), "=r"(r[2]), "=r"(r[3]) : "r"(addr));
}
__device__ __forceinline__ uint32_t pack_h2(float lo, float hi) {
    __half2 h = __floats2half2_rn(lo, hi);
    return *reinterpret_cast<uint32_t*>(&h);
}

// ======================= weight transpose -> fp16 ==========================
__global__ void wtrans16(const float* __restrict__ in, __half* __restrict__ oh,
                         int K, int N) {
    __shared__ float tile[32][33];
    const int k0 = blockIdx.y * 32, n0 = blockIdx.x * 32;
    const int tx = threadIdx.x, ty = threadIdx.y;
    #pragma unroll
    for (int i = ty; i < 32; i += 8)
        tile[i][tx] = in[(size_t)(k0 + i) * N + n0 + tx];
    __syncthreads();
    #pragma unroll
    for (int i = ty; i < 32; i += 8)
        oh[(size_t)(n0 + i) * K + k0 + tx] = __float2half_rn(tile[tx][i]);
}

// ======================= fp32 -> fp16 convert ==============================
__global__ void f2h(const float* __restrict__ in, __half* __restrict__ out) {
    const int i = (blockIdx.x * blockDim.x + threadIdx.x) * 4;
    float4 v = *reinterpret_cast<const float4*>(in + i);
    __half2 a = __floats2half2_rn(v.x, v.y);
    __half2 b = __floats2half2_rn(v.z, v.w);
    uint2 pk;
    pk.x = *reinterpret_cast<uint32_t*>(&a);
    pk.y = *reinterpret_cast<uint32_t*>(&b);
    *reinterpret_cast<uint2*>(out + i) = pk;
}

// ======================= plain fp16 GEMM (128x128, BK=64, 2-stage) =========
#define ASTR 72                              // 64 data + 8 pad halves
#define GEMM_STAGE (2 * 128 * ASTR)          // 18432 halves = 36864 B
#define GEMM_SMEM  73728

__global__ __launch_bounds__(256)
void gemm_f16(const __half* __restrict__ A, const __half* __restrict__ B,
              const float* __restrict__ bias, float* __restrict__ C,
              int M, int N, int K)
{
    extern __shared__ __half smh[];
    const int tid  = threadIdx.x;
    const int warp = tid >> 5, lane = tid & 31;
    const int gid  = lane >> 2, t4 = lane & 3;
    const int mrow = lane & 7, msel = lane >> 3;
    const int wm0  = (warp & 3) * 32;
    const int wn0  = (warp >> 2) * 64;
    const int bx = blockIdx.x, by = blockIdx.y;

    const __half* Ab = A + (size_t)by * 128 * K;
    const __half* Bb = B + (size_t)bx * 128 * K;
    const int NS = K / 64;
    const uint32_t sb = smem_u32(smh);

    auto load_stage = [&](int s, int ks) {
        #pragma unroll
        for (int i = 0; i < 8; i++) {
            const int id  = tid + i * 256;
            const int isB = id >= 1024;
            const int id2 = isB ? id - 1024 : id;
            const int row = id2 >> 3;
            const int c8  = (id2 & 7) * 8;
            const __half* src = (isB ? Bb : Ab) + (size_t)row * K + ks * 64 + c8;
            const uint32_t dst = sb +
                (uint32_t)(s * GEMM_STAGE + isB * 128 * ASTR + row * ASTR + c8) * 2u;
            cp16(dst, src);
        }
        CP_COMMIT();
    };

    float acc[2][8][4];
    #pragma unroll
    for (int mt = 0; mt < 2; mt++)
        #pragma unroll
        for (int nt = 0; nt < 8; nt++)
            #pragma unroll
            for (int r = 0; r < 4; r++) acc[mt][nt][r] = 0.f;

    load_stage(0, 0);
    for (int ks = 0; ks < NS; ks++) {
        const int s = ks & 1;
        if (ks + 1 < NS) { load_stage(1 - s, ks + 1); CP_WAIT(1); }
        else             { CP_WAIT(0); }
        __syncthreads();

        const uint32_t uA = sb + (uint32_t)(s * GEMM_STAGE) * 2u;
        const uint32_t uB = uA + (uint32_t)(128 * ASTR) * 2u;

        #pragma unroll
        for (int kk = 0; kk < 4; kk++) {
            const int kb = kk * 16;
            uint32_t a0[4], a1[4];
            const uint32_t aoff = (uint32_t)((wm0 + (lane & 15)) * ASTR + kb
                                             + ((lane & 16) ? 8 : 0)) * 2u;
            ldsm4(a0, uA + aoff);
            ldsm4(a1, uA + aoff + (uint32_t)(16 * ASTR) * 2u);
            #pragma unroll
            for (int np = 0; np < 4; np++) {
                const uint32_t boff = (uint32_t)((wn0 + np * 16 + (msel >> 1) * 8 + mrow) * ASTR
                                                 + kb + (msel & 1) * 8) * 2u;
                uint32_t b4[4];
                ldsm4(b4, uB + boff);
                mma_f16(acc[0][2 * np],     a0, b4 + 0);
                mma_f16(acc[0][2 * np + 1], a0, b4 + 2);
                mma_f16(acc[1][2 * np],     a1, b4 + 0);
                mma_f16(acc[1][2 * np + 1], a1, b4 + 2);
            }
        }
        __syncthreads();
    }

    float* Cs = reinterpret_cast<float*>(smh);
    #pragma unroll
    for (int mt = 0; mt < 2; mt++)
        #pragma unroll
        for (int nt = 0; nt < 8; nt++) {
            const int row = wm0 + mt * 16 + gid;
            const int col = wn0 + nt * 8 + t4 * 2;
            Cs[row * 132 + col]           = acc[mt][nt][0];
            Cs[row * 132 + col + 1]       = acc[mt][nt][1];
            Cs[(row + 8) * 132 + col]     = acc[mt][nt][2];
            Cs[(row + 8) * 132 + col + 1] = acc[mt][nt][3];
        }
    __syncthreads();
    #pragma unroll
    for (int it = 0; it < 16; it++) {
        const int id  = tid + it * 256;
        const int row = id >> 5;
        const int c4  = (id & 31) * 4;
        float4 v = *reinterpret_cast<const float4*>(&Cs[row * 132 + c4]);
        const int gc = bx * 128 + c4;
        v.x += bias[gc + 0]; v.y += bias[gc + 1]; v.z += bias[gc + 2]; v.w += bias[gc + 3];
        *reinterpret_cast<float4*>(&C[(size_t)(by * 128 + row) * N + gc]) = v;
    }
}

// ======================= RoPE + split-scatter ==============================
__global__ void rope_scatter(const float* __restrict__ qkv,
                             const float* __restrict__ freqs,
                             __half* __restrict__ Qh, __half* __restrict__ Ql,
                             __half* __restrict__ Kh, __half* __restrict__ Kl,
                             int S)
{
    const int s = blockIdx.x;
    const float* base = qkv + (size_t)s * (3 * D_MODEL);
    const float scale = 0.11180339887498949f;   // 1/sqrt(80)
    for (int idx = threadIdx.x; idx < NHEADS * HDIM; idx += blockDim.x) {
        const int h = idx / HDIM;
        const int d = idx % HDIM;
        const int dd = (d < 40) ? d : d - 40;
        const float f  = freqs[(size_t)s * 40 + dd];
        const float cs = cosf(f), sn = sinf(f);
        const float q1 = base[h * HDIM + dd];
        const float q2 = base[h * HDIM + dd + 40];
        const float k1 = base[D_MODEL + h * HDIM + dd];
        const float k2 = base[D_MODEL + h * HDIM + dd + 40];
        float qo = (d < 40) ? (q1 * cs - q2 * sn) : (q1 * sn + q2 * cs);
        const float ko = (d < 40) ? (k1 * cs - k2 * sn) : (k1 * sn + k2 * cs);
        qo *= scale;
        const size_t o = ((size_t)h * S + s) * HDIM + d;
        const __half qhi = __float2half_rn(qo);
        Qh[o] = qhi;
        Ql[o] = __float2half_rn(qo - __half2float(qhi));
        const __half khi = __float2half_rn(ko);
        Kh[o] = khi;
        Kl[o] = __float2half_rn(ko - __half2float(khi));
    }
}

// ======================= V transpose (fp16 hi only) ========================
__global__ void vtrans(const float* __restrict__ qkv,
                       __half* __restrict__ Vh, int S)
{
    __shared__ float tile[64][84];
    const int tid = threadIdx.x;
    const int h  = blockIdx.y;
    const int s0 = blockIdx.x * 64;
    {
        const int sl = tid >> 2;
        const int dc = (tid & 3) * 20;
        const float* src = qkv + (size_t)(s0 + sl) * (3 * D_MODEL) + 2 * D_MODEL + h * HDIM + dc;
        #pragma unroll
        for (int i = 0; i < 5; i++) {
            float4 v = *reinterpret_cast<const float4*>(src + i * 4);
            tile[sl][dc + i * 4 + 0] = v.x;
            tile[sl][dc + i * 4 + 1] = v.y;
            tile[sl][dc + i * 4 + 2] = v.z;
            tile[sl][dc + i * 4 + 3] = v.w;
        }
    }
    __syncthreads();
    if (tid < 160) {
        const int d  = tid >> 1;
        const int sh = (tid & 1) * 32;
        const size_t o = ((size_t)(h * HDIM + d)) * S + s0 + sh;
        #pragma unroll
        for (int j = 0; j < 16; j++) {
            __half2 hv = __floats2half2_rn(tile[sh + 2 * j][d], tile[sh + 2 * j + 1][d]);
            *reinterpret_cast<__half2*>(&Vh[o + 2 * j]) = hv;
        }
    }
}

// ======================= fp16-split tensor-core attention ==================
// CTA = (q-tile 256, head), 16 warps x 16 q-rows, KV tile 64, 2-stage cp.async.
// QK^T: 3-MMA hi/lo split. PV: plain fp16 V (1 MMA).
#define QSTR 88
#define VSTR 72
#define ATT_Q  (256 * QSTR)
#define ATT_K  (64 * QSTR)
#define ATT_V  (80 * VSTR)
#define ATC_SMEM ((2 * ATT_Q + 4 * ATT_K + 2 * ATT_V) * 2)   // 158208 B

__global__ __launch_bounds__(512)
void attn_tc(const __half* __restrict__ gQh, const __half* __restrict__ gQl,
             const __half* __restrict__ gKh, const __half* __restrict__ gKl,
             const __half* __restrict__ gVh,
             const int* __restrict__ cu, int n_seg,
             __half* __restrict__ outh, int S)
{
    extern __shared__ __half sh[];
    __half* Qh = sh;
    __half* Ql = Qh + ATT_Q;
    __half* Kh = Ql + ATT_Q;           // [2][ATT_K]
    __half* Kl = Kh + 2 * ATT_K;
    __half* Vh = Kl + 2 * ATT_K;       // [2][ATT_V]

    const uint32_t uQh = smem_u32(Qh), uQl = smem_u32(Ql);
    const uint32_t uKh = smem_u32(Kh), uKl = smem_u32(Kl);
    const uint32_t uVh = smem_u32(Vh);

    const int tid  = threadIdx.x;
    const int warp = tid >> 5, lane = tid & 31;
    const int gid  = lane >> 2, t4 = lane & 3;
    const int mrow = lane & 7, msel = lane >> 3;
    const int wq   = warp * 16;
    const int h    = blockIdx.y;
    const int q0   = blockIdx.x * 256;

    int start = 0, end = S;
    for (int i = 0; i < n_seg; i++) {
        int a = cu[i], b = cu[i + 1];
        if (a <= q0 && q0 < b) { start = a; end = b; }
    }

    // ---- Q load (cp.async) ----
    #pragma unroll
    for (int i = 0; i < 10; i++) {
        const int id  = tid + i * 512;        // 0..5119
        const int isL = id >= 2560;
        const int id2 = isL ? id - 2560 : id;
        const int r   = id2 / 10;
        const int c8  = (id2 % 10) * 8;
        const size_t so = ((size_t)h * S + q0 + r) * HDIM + c8;
        const uint32_t dst = (isL ? uQl : uQh) + (uint32_t)(r * QSTR + c8) * 2u;
        cp16(dst, (isL ? gQl : gQh) + so);
    }

    const int nkt = (end - start + 63) / 64;

    // KV loader: K hi+lo (1280 chunks) + V hi (640 chunks) = 1920
    auto load_kv = [&](int st, int t) {
        const int k0 = start + t * 64;
        #pragma unroll
        for (int i = 0; i < 4; i++) {
            const int id = tid + i * 512;     // 0..2047
            if (id < 1280) {                  // K
                const int isL = id >= 640;
                const int id2 = isL ? id - 640 : id;
                const int r   = id2 / 10;
                const int c8  = (id2 % 10) * 8;
                const size_t so = ((size_t)h * S + k0 + r) * HDIM + c8;
                const uint32_t dst = (isL ? uKl : uKh) +
                    (uint32_t)(st * ATT_K + r * QSTR + c8) * 2u;
                cp16(dst, (isL ? gKl : gKh) + so);
            } else if (id < 1920) {           // V hi
                const int idv = id - 1280;
                const int r   = idv >> 3;
                const int c8  = (idv & 7) * 8;
                const size_t so = ((size_t)(h * HDIM + r)) * S + k0 + c8;
                const uint32_t dst = uVh +
                    (uint32_t)(st * ATT_V + r * VSTR + c8) * 2u;
                cp16(dst, gVh + so);
            }
        }
        CP_COMMIT();
    };

    load_kv(0, 0);

    float acc_o[10][4];
    #pragma unroll
    for (int n = 0; n < 10; n++)
        #pragma unroll
        for (int r = 0; r < 4; r++) acc_o[n][r] = 0.f;
    float m0 = -INFINITY, m1 = -INFINITY, l0 = 0.f, l1 = 0.f;

    for (int t = 0; t < nkt; t++) {
        const int b = t & 1;
        if (t + 1 < nkt) { load_kv(1 - b, t + 1); CP_WAIT(1); }
        else             { CP_WAIT(0); }
        __syncthreads();

        const uint32_t kB = (uint32_t)(b * ATT_K) * 2u;
        const uint32_t vB = (uint32_t)(b * ATT_V) * 2u;

        // ---- QK^T: 5 k16-blocks, 3-MMA hi/lo split ----
        float acc_s[8][4];
        #pragma unroll
        for (int n = 0; n < 8; n++)
            #pragma unroll
            for (int r = 0; r < 4; r++) acc_s[n][r] = 0.f;

        #pragma unroll
        for (int kk = 0; kk < 5; kk++) {
            const int kb = kk * 16;
            uint32_t ah[4], al[4];
            {
                const uint32_t off = (uint32_t)((wq + (lane & 15)) * QSTR + kb
                                                + ((lane & 16) ? 8 : 0)) * 2u;
                ldsm4(ah, uQh + off);
                ldsm4(al, uQl + off);
            }
            #pragma unroll
            for (int np = 0; np < 4; np++) {
                const uint32_t off = (uint32_t)((np * 16 + (msel >> 1) * 8 + mrow) * QSTR
                                                + kb + (msel & 1) * 8) * 2u;
                uint32_t bh4[4], bl4[4];
                ldsm4(bh4, uKh + kB + off);
                ldsm4(bl4, uKl + kB + off);
                mma_f16(acc_s[2 * np],     ah, bh4 + 0);
                mma_f16(acc_s[2 * np],     al, bh4 + 0);
                mma_f16(acc_s[2 * np],     ah, bl4 + 0);
                mma_f16(acc_s[2 * np + 1], ah, bh4 + 2);
                mma_f16(acc_s[2 * np + 1], al, bh4 + 2);
                mma_f16(acc_s[2 * np + 1], ah, bl4 + 2);
            }
        }

        // ---- mask + online softmax ----
        const int k0 = start + t * 64;
        const int nv = end - k0;
        float mt0 = -INFINITY, mt1 = -INFINITY;
        #pragma unroll
        for (int nt = 0; nt < 8; nt++) {
            #pragma unroll
            for (int j = 0; j < 2; j++) {
                const int c = nt * 8 + 2 * t4 + j;
                if (c >= nv) { acc_s[nt][j] = -1e30f; acc_s[nt][2 + j] = -1e30f; }
                mt0 = fmaxf(mt0, acc_s[nt][j]);
                mt1 = fmaxf(mt1, acc_s[nt][2 + j]);
            }
        }
        mt0 = fmaxf(mt0, __shfl_xor_sync(0xffffffffu, mt0, 1));
        mt0 = fmaxf(mt0, __shfl_xor_sync(0xffffffffu, mt0, 2));
        mt1 = fmaxf(mt1, __shfl_xor_sync(0xffffffffu, mt1, 1));
        mt1 = fmaxf(mt1, __shfl_xor_sync(0xffffffffu, mt1, 2));

        const float mn0 = fmaxf(m0, mt0), mn1 = fmaxf(m1, mt1);
        const float al0 = __expf(m0 - mn0), al1 = __expf(m1 - mn1);
        m0 = mn0; m1 = mn1;

        float rs0 = 0.f, rs1 = 0.f;
        #pragma unroll
        for (int nt = 0; nt < 8; nt++) {
            #pragma unroll
            for (int j = 0; j < 2; j++) {
                const float p0 = __expf(acc_s[nt][j]     - m0);
                const float p1 = __expf(acc_s[nt][2 + j] - m1);
                acc_s[nt][j]     = p0;
                acc_s[nt][2 + j] = p1;
                rs0 += p0; rs1 += p1;
            }
        }
        rs0 += __shfl_xor_sync(0xffffffffu, rs0, 1);
        rs0 += __shfl_xor_sync(0xffffffffu, rs0, 2);
        rs1 += __shfl_xor_sync(0xffffffffu, rs1, 1);
        rs1 += __shfl_xor_sync(0xffffffffu, rs1, 2);
        l0 = l0 * al0 + rs0;
        l1 = l1 * al1 + rs1;

        #pragma unroll
        for (int n = 0; n < 10; n++) {
            acc_o[n][0] *= al0; acc_o[n][1] *= al0;
            acc_o[n][2] *= al1; acc_o[n][3] *= al1;
        }

        // ---- pack P into fp16 A-fragments ----
        uint32_t pk[4][4];
        #pragma unroll
        for (int kk = 0; kk < 4; kk++) {
            pk[kk][0] = pack_h2(acc_s[2 * kk][0],     acc_s[2 * kk][1]);
            pk[kk][1] = pack_h2(acc_s[2 * kk][2],     acc_s[2 * kk][3]);
            pk[kk][2] = pack_h2(acc_s[2 * kk + 1][0], acc_s[2 * kk + 1][1]);
            pk[kk][3] = pack_h2(acc_s[2 * kk + 1][2], acc_s[2 * kk + 1][3]);
        }

        // ---- PV: 4 k16-blocks, plain fp16 V ----
        #pragma unroll
        for (int kk = 0; kk < 4; kk++) {
            const int kb = kk * 16;
            #pragma unroll
            for (int vp = 0; vp < 5; vp++) {
                const uint32_t off = (uint32_t)((vp * 16 + (msel >> 1) * 8 + mrow) * VSTR
                                                + kb + (msel & 1) * 8) * 2u;
                uint32_t vh4[4];
                ldsm4(vh4, uVh + vB + off);
                mma_f16(acc_o[2 * vp],     pk[kk], vh4 + 0);
                mma_f16(acc_o[2 * vp + 1], pk[kk], vh4 + 2);
            }
        }
        __syncthreads();
    }

    // ---- epilogue: write fp16 ----
    const float inv0 = 1.f / l0, inv1 = 1.f / l1;
    const int r0 = q0 + wq + gid, r1 = r0 + 8;
    #pragma unroll
    for (int nt = 0; nt < 10; nt++) {
        const int col = h * HDIM + nt * 8 + 2 * t4;
        __half2 v0 = __floats2half2_rn(acc_o[nt][0] * inv0, acc_o[nt][1] * inv0);
        __half2 v1 = __floats2half2_rn(acc_o[nt][2] * inv1, acc_o[nt][3] * inv1);
        *reinterpret_cast<__half2*>(&outh[(size_t)r0 * D_MODEL + col]) = v0;
        *reinterpret_cast<__half2*>(&outh[(size_t)r1 * D_MODEL + col]) = v1;
    }
}

// ======================= launch ============================================
extern "C" void kernel_launch(void* const* d_in, const int* in_sizes, int n_in,
                              void* d_out, int out_size)
{
    const float* hidden = (const float*)d_in[0];
    const int*   cu     = (const int*)  d_in[1];
    const float* rope   = (const float*)d_in[2];
    const float* w_qkv  = (const float*)d_in[3];
    const float* b_qkv  = (const float*)d_in[4];
    const float* w_proj = (const float*)d_in[5];
    const float* b_proj = (const float*)d_in[6];
    float* out = (float*)d_out;

    const int S     = in_sizes[0] / D_MODEL;
    const int n_seg = in_sizes[1] - 1;

    float *qkv_p;
    __half *hh, *attnh, *wqh, *wph, *qh, *ql, *kh, *kl, *vh;
    cudaGetSymbolAddress((void**)&qkv_p, g_qkv);
    cudaGetSymbolAddress((void**)&hh,    g_hh);
    cudaGetSymbolAddress((void**)&attnh, g_attnh);
    cudaGetSymbolAddress((void**)&wqh,   g_wqkv_h);
    cudaGetSymbolAddress((void**)&wph,   g_wproj_h);
    cudaGetSymbolAddress((void**)&qh, g_qh);
    cudaGetSymbolAddress((void**)&ql, g_ql);
    cudaGetSymbolAddress((void**)&kh, g_kh);
    cudaGetSymbolAddress((void**)&kl, g_kl);
    cudaGetSymbolAddress((void**)&vh, g_vh);

    cudaFuncSetAttribute(gemm_f16, cudaFuncAttributeMaxDynamicSharedMemorySize, GEMM_SMEM);
    cudaFuncSetAttribute(attn_tc,  cudaFuncAttributeMaxDynamicSharedMemorySize, ATC_SMEM);

    // 0) weight transpose -> fp16; hidden -> fp16
    {
        dim3 blk(32, 8);
        wtrans16<<<dim3(3 * D_MODEL / 32, D_MODEL / 32), blk>>>(w_qkv, wqh, D_MODEL, 3 * D_MODEL);
        wtrans16<<<dim3(D_MODEL / 32, D_MODEL / 32), blk>>>(w_proj, wph, D_MODEL, D_MODEL);
        f2h<<<(S * D_MODEL) / (256 * 4), 256>>>(hidden, hh);
    }

    // 1) QKV projection (plain fp16, BK=64)
    gemm_f16<<<dim3(3 * D_MODEL / 128, S / 128), 256, GEMM_SMEM>>>(
        hh, wqh, b_qkv, qkv_p, S, 3 * D_MODEL, D_MODEL);

    // 2) RoPE split scatter; V transpose (hi only)
    rope_scatter<<<S, 256>>>(qkv_p, rope, qh, ql, kh, kl, S);
    vtrans<<<dim3(S / 64, NHEADS), 256>>>(qkv_p, vh, S);

    // 3) block-diagonal attention (V hi only)
    attn_tc<<<dim3(S / 256, NHEADS), 512, ATC_SMEM>>>(
        qh, ql, kh, kl, vh, cu, n_seg, attnh, S);

    // 4) output projection (plain fp16, BK=64)
    gemm_f16<<<dim3(D_MODEL / 128, S / 128), 256, GEMM_SMEM>>>(
        attnh, wph, b_proj, out, S, D_MODEL, D_MODEL);
}

// round 15
// speedup vs baseline: 1.3806x; 1.0743x over previous
#include <cuda_runtime.h>
#include <cuda_fp16.h>
#include <math.h>
#include <cstdint>

#define D_MODEL 1280
#define NHEADS  16
#define HDIM    80
#define S_MAX   4096

// ---------------- scratch (device globals; no allocation allowed) ----------
__device__ float  g_qkv[S_MAX * 3 * D_MODEL];
__device__ __half g_hh[S_MAX * D_MODEL];                 // hidden fp16
__device__ __half g_attnh[S_MAX * D_MODEL];              // attn out fp16
__device__ __half g_wqkv_h[3 * D_MODEL * D_MODEL];       // (3D, D) K-major fp16
__device__ __half g_wproj_h[D_MODEL * D_MODEL];
// fp16 attention tensors (Q hi+lo split, K hi, V hi)
__device__ __half g_qh[NHEADS * S_MAX * HDIM];           // (H,S,80) scaled
__device__ __half g_ql[NHEADS * S_MAX * HDIM];
__device__ __half g_kh[NHEADS * S_MAX * HDIM];
__device__ __half g_vh[NHEADS * HDIM * S_MAX];           // (H,80,S) transposed

// ======================= helpers ===========================================
__device__ __forceinline__ uint32_t smem_u32(const void* p) {
    uint32_t a;
    asm("{ .reg .u64 t; cvta.to.shared.u64 t, %1; cvt.u32.u64 %0, t; }" : "=r"(a) : "l"(p));
    return a;
}
__device__ __forceinline__ void cp16(uint32_t dst, const void* src) {
    asm volatile("cp.async.cg.shared.global [%0], [%1], 16;" :: "r"(dst), "l"(src));
}
#define CP_COMMIT() asm volatile("cp.async.commit_group;" ::: "memory")
#define CP_WAIT(n)  asm volatile("cp.async.wait_group %0;" :: "n"(n) : "memory")

__device__ __forceinline__ void mma_f16(float* c, const uint32_t* a, const uint32_t* b) {
    asm volatile(
        "mma.sync.aligned.m16n8k16.row.col.f32.f16.f16.f32 "
        "{%0,%1,%2,%3}, {%4,%5,%6,%7}, {%8,%9}, {%0,%1,%2,%3};"
        : "+f"(c[0]), "+f"(c[1]), "+f"(c[2]), "+f"(c[3])
        : "r"(a[0]), "r"(a[1]), "r"(a[2]), "r"(a[3]), "r"(b[0]), "r"(b[1]));
}
__device__ __forceinline__ void ldsm4(uint32_t* r, uint32_t addr) {
    asm volatile("ldmatrix.sync.aligned.m8n8.x4.shared.b16 {%0,%1,%2,%3}, [%4];"
        : "=r"(r[0]), "=r"(r[1]), "=r"(r[2]), "=r"(r[3]) : "r"(addr));
}
__device__ __forceinline__ uint32_t pack_h2(float lo, float hi) {
    __half2 h = __floats2half2_rn(lo, hi);
    return *reinterpret_cast<uint32_t*>(&h);
}

// ======================= weight transpose -> fp16 ==========================
__global__ void wtrans16(const float* __restrict__ in, __half* __restrict__ oh,
                         int K, int N) {
    __shared__ float tile[32][33];
    const int k0 = blockIdx.y * 32, n0 = blockIdx.x * 32;
    const int tx = threadIdx.x, ty = threadIdx.y;
    #pragma unroll
    for (int i = ty; i < 32; i += 8)
        tile[i][tx] = in[(size_t)(k0 + i) * N + n0 + tx];
    __syncthreads();
    #pragma unroll
    for (int i = ty; i < 32; i += 8)
        oh[(size_t)(n0 + i) * K + k0 + tx] = __float2half_rn(tile[tx][i]);
}

// ======================= fp32 -> fp16 convert ==============================
__global__ void f2h(const float* __restrict__ in, __half* __restrict__ out) {
    const int i = (blockIdx.x * blockDim.x + threadIdx.x) * 4;
    float4 v = *reinterpret_cast<const float4*>(in + i);
    __half2 a = __floats2half2_rn(v.x, v.y);
    __half2 b = __floats2half2_rn(v.z, v.w);
    uint2 pk;
    pk.x = *reinterpret_cast<uint32_t*>(&a);
    pk.y = *reinterpret_cast<uint32_t*>(&b);
    *reinterpret_cast<uint2*>(out + i) = pk;
}

// ======================= plain fp16 GEMM (128x128, BK=64, 2-stage) =========
#define ASTR 72                              // 64 data + 8 pad halves
#define GEMM_STAGE (2 * 128 * ASTR)          // 18432 halves = 36864 B
#define GEMM_SMEM  73728

__global__ __launch_bounds__(256)
void gemm_f16(const __half* __restrict__ A, const __half* __restrict__ B,
              const float* __restrict__ bias, float* __restrict__ C,
              int M, int N, int K)
{
    extern __shared__ __half smh[];
    const int tid  = threadIdx.x;
    const int warp = tid >> 5, lane = tid & 31;
    const int gid  = lane >> 2, t4 = lane & 3;
    const int mrow = lane & 7, msel = lane >> 3;
    const int wm0  = (warp & 3) * 32;
    const int wn0  = (warp >> 2) * 64;
    const int bx = blockIdx.x, by = blockIdx.y;

    const __half* Ab = A + (size_t)by * 128 * K;
    const __half* Bb = B + (size_t)bx * 128 * K;
    const int NS = K / 64;
    const uint32_t sb = smem_u32(smh);

    auto load_stage = [&](int s, int ks) {
        #pragma unroll
        for (int i = 0; i < 8; i++) {
            const int id  = tid + i * 256;
            const int isB = id >= 1024;
            const int id2 = isB ? id - 1024 : id;
            const int row = id2 >> 3;
            const int c8  = (id2 & 7) * 8;
            const __half* src = (isB ? Bb : Ab) + (size_t)row * K + ks * 64 + c8;
            const uint32_t dst = sb +
                (uint32_t)(s * GEMM_STAGE + isB * 128 * ASTR + row * ASTR + c8) * 2u;
            cp16(dst, src);
        }
        CP_COMMIT();
    };

    float acc[2][8][4];
    #pragma unroll
    for (int mt = 0; mt < 2; mt++)
        #pragma unroll
        for (int nt = 0; nt < 8; nt++)
            #pragma unroll
            for (int r = 0; r < 4; r++) acc[mt][nt][r] = 0.f;

    load_stage(0, 0);
    for (int ks = 0; ks < NS; ks++) {
        const int s = ks & 1;
        if (ks + 1 < NS) { load_stage(1 - s, ks + 1); CP_WAIT(1); }
        else             { CP_WAIT(0); }
        __syncthreads();

        const uint32_t uA = sb + (uint32_t)(s * GEMM_STAGE) * 2u;
        const uint32_t uB = uA + (uint32_t)(128 * ASTR) * 2u;

        #pragma unroll
        for (int kk = 0; kk < 4; kk++) {
            const int kb = kk * 16;
            uint32_t a0[4], a1[4];
            const uint32_t aoff = (uint32_t)((wm0 + (lane & 15)) * ASTR + kb
                                             + ((lane & 16) ? 8 : 0)) * 2u;
            ldsm4(a0, uA + aoff);
            ldsm4(a1, uA + aoff + (uint32_t)(16 * ASTR) * 2u);
            #pragma unroll
            for (int np = 0; np < 4; np++) {
                const uint32_t boff = (uint32_t)((wn0 + np * 16 + (msel >> 1) * 8 + mrow) * ASTR
                                                 + kb + (msel & 1) * 8) * 2u;
                uint32_t b4[4];
                ldsm4(b4, uB + boff);
                mma_f16(acc[0][2 * np],     a0, b4 + 0);
                mma_f16(acc[0][2 * np + 1], a0, b4 + 2);
                mma_f16(acc[1][2 * np],     a1, b4 + 0);
                mma_f16(acc[1][2 * np + 1], a1, b4 + 2);
            }
        }
        __syncthreads();
    }

    float* Cs = reinterpret_cast<float*>(smh);
    #pragma unroll
    for (int mt = 0; mt < 2; mt++)
        #pragma unroll
        for (int nt = 0; nt < 8; nt++) {
            const int row = wm0 + mt * 16 + gid;
            const int col = wn0 + nt * 8 + t4 * 2;
            Cs[row * 132 + col]           = acc[mt][nt][0];
            Cs[row * 132 + col + 1]       = acc[mt][nt][1];
            Cs[(row + 8) * 132 + col]     = acc[mt][nt][2];
            Cs[(row + 8) * 132 + col + 1] = acc[mt][nt][3];
        }
    __syncthreads();
    #pragma unroll
    for (int it = 0; it < 16; it++) {
        const int id  = tid + it * 256;
        const int row = id >> 5;
        const int c4  = (id & 31) * 4;
        float4 v = *reinterpret_cast<const float4*>(&Cs[row * 132 + c4]);
        const int gc = bx * 128 + c4;
        v.x += bias[gc + 0]; v.y += bias[gc + 1]; v.z += bias[gc + 2]; v.w += bias[gc + 3];
        *reinterpret_cast<float4*>(&C[(size_t)(by * 128 + row) * N + gc]) = v;
    }
}

// ======================= RoPE + split-scatter ==============================
// Q -> hi/lo split (scaled); K -> plain fp16 hi.
__global__ void rope_scatter(const float* __restrict__ qkv,
                             const float* __restrict__ freqs,
                             __half* __restrict__ Qh, __half* __restrict__ Ql,
                             __half* __restrict__ Kh,
                             int S)
{
    const int s = blockIdx.x;
    const float* base = qkv + (size_t)s * (3 * D_MODEL);
    const float scale = 0.11180339887498949f;   // 1/sqrt(80)
    for (int idx = threadIdx.x; idx < NHEADS * HDIM; idx += blockDim.x) {
        const int h = idx / HDIM;
        const int d = idx % HDIM;
        const int dd = (d < 40) ? d : d - 40;
        const float f  = freqs[(size_t)s * 40 + dd];
        const float cs = cosf(f), sn = sinf(f);
        const float q1 = base[h * HDIM + dd];
        const float q2 = base[h * HDIM + dd + 40];
        const float k1 = base[D_MODEL + h * HDIM + dd];
        const float k2 = base[D_MODEL + h * HDIM + dd + 40];
        float qo = (d < 40) ? (q1 * cs - q2 * sn) : (q1 * sn + q2 * cs);
        const float ko = (d < 40) ? (k1 * cs - k2 * sn) : (k1 * sn + k2 * cs);
        qo *= scale;
        const size_t o = ((size_t)h * S + s) * HDIM + d;
        const __half qhi = __float2half_rn(qo);
        Qh[o] = qhi;
        Ql[o] = __float2half_rn(qo - __half2float(qhi));
        Kh[o] = __float2half_rn(ko);
    }
}

// ======================= V transpose (fp16 hi only) ========================
__global__ void vtrans(const float* __restrict__ qkv,
                       __half* __restrict__ Vh, int S)
{
    __shared__ float tile[64][84];
    const int tid = threadIdx.x;
    const int h  = blockIdx.y;
    const int s0 = blockIdx.x * 64;
    {
        const int sl = tid >> 2;
        const int dc = (tid & 3) * 20;
        const float* src = qkv + (size_t)(s0 + sl) * (3 * D_MODEL) + 2 * D_MODEL + h * HDIM + dc;
        #pragma unroll
        for (int i = 0; i < 5; i++) {
            float4 v = *reinterpret_cast<const float4*>(src + i * 4);
            tile[sl][dc + i * 4 + 0] = v.x;
            tile[sl][dc + i * 4 + 1] = v.y;
            tile[sl][dc + i * 4 + 2] = v.z;
            tile[sl][dc + i * 4 + 3] = v.w;
        }
    }
    __syncthreads();
    if (tid < 160) {
        const int d  = tid >> 1;
        const int sh = (tid & 1) * 32;
        const size_t o = ((size_t)(h * HDIM + d)) * S + s0 + sh;
        #pragma unroll
        for (int j = 0; j < 16; j++) {
            __half2 hv = __floats2half2_rn(tile[sh + 2 * j][d], tile[sh + 2 * j + 1][d]);
            *reinterpret_cast<__half2*>(&Vh[o + 2 * j]) = hv;
        }
    }
}

// ======================= fp16-split tensor-core attention ==================
// CTA = (q-tile 256, head), 16 warps x 16 q-rows, KV tile 64, 2-stage cp.async.
// QK^T: 2-MMA Q hi/lo split (K plain fp16). PV: plain fp16 V (1 MMA).
#define QSTR 88
#define VSTR 72
#define ATT_Q  (256 * QSTR)
#define ATT_K  (64 * QSTR)
#define ATT_V  (80 * VSTR)
#define ATC_SMEM ((2 * ATT_Q + 2 * ATT_K + 2 * ATT_V) * 2)   // 135680 B

__global__ __launch_bounds__(512)
void attn_tc(const __half* __restrict__ gQh, const __half* __restrict__ gQl,
             const __half* __restrict__ gKh,
             const __half* __restrict__ gVh,
             const int* __restrict__ cu, int n_seg,
             __half* __restrict__ outh, int S)
{
    extern __shared__ __half sh[];
    __half* Qh = sh;
    __half* Ql = Qh + ATT_Q;
    __half* Kh = Ql + ATT_Q;           // [2][ATT_K]
    __half* Vh = Kh + 2 * ATT_K;       // [2][ATT_V]

    const uint32_t uQh = smem_u32(Qh), uQl = smem_u32(Ql);
    const uint32_t uKh = smem_u32(Kh);
    const uint32_t uVh = smem_u32(Vh);

    const int tid  = threadIdx.x;
    const int warp = tid >> 5, lane = tid & 31;
    const int gid  = lane >> 2, t4 = lane & 3;
    const int mrow = lane & 7, msel = lane >> 3;
    const int wq   = warp * 16;
    const int h    = blockIdx.y;
    const int q0   = blockIdx.x * 256;

    int start = 0, end = S;
    for (int i = 0; i < n_seg; i++) {
        int a = cu[i], b = cu[i + 1];
        if (a <= q0 && q0 < b) { start = a; end = b; }
    }

    // ---- Q load (cp.async) ----
    #pragma unroll
    for (int i = 0; i < 10; i++) {
        const int id  = tid + i * 512;        // 0..5119
        const int isL = id >= 2560;
        const int id2 = isL ? id - 2560 : id;
        const int r   = id2 / 10;
        const int c8  = (id2 % 10) * 8;
        const size_t so = ((size_t)h * S + q0 + r) * HDIM + c8;
        const uint32_t dst = (isL ? uQl : uQh) + (uint32_t)(r * QSTR + c8) * 2u;
        cp16(dst, (isL ? gQl : gQh) + so);
    }

    const int nkt = (end - start + 63) / 64;

    // KV loader: K hi (640 chunks) + V hi (640 chunks) = 1280
    auto load_kv = [&](int st, int t) {
        const int k0 = start + t * 64;
        #pragma unroll
        for (int i = 0; i < 3; i++) {
            const int id = tid + i * 512;     // 0..1535
            if (id < 640) {                   // K hi
                const int r   = id / 10;
                const int c8  = (id % 10) * 8;
                const size_t so = ((size_t)h * S + k0 + r) * HDIM + c8;
                const uint32_t dst = uKh +
                    (uint32_t)(st * ATT_K + r * QSTR + c8) * 2u;
                cp16(dst, gKh + so);
            } else if (id < 1280) {           // V hi
                const int idv = id - 640;
                const int r   = idv >> 3;
                const int c8  = (idv & 7) * 8;
                const size_t so = ((size_t)(h * HDIM + r)) * S + k0 + c8;
                const uint32_t dst = uVh +
                    (uint32_t)(st * ATT_V + r * VSTR + c8) * 2u;
                cp16(dst, gVh + so);
            }
        }
        CP_COMMIT();
    };

    load_kv(0, 0);

    float acc_o[10][4];
    #pragma unroll
    for (int n = 0; n < 10; n++)
        #pragma unroll
        for (int r = 0; r < 4; r++) acc_o[n][r] = 0.f;
    float m0 = -INFINITY, m1 = -INFINITY, l0 = 0.f, l1 = 0.f;

    for (int t = 0; t < nkt; t++) {
        const int b = t & 1;
        if (t + 1 < nkt) { load_kv(1 - b, t + 1); CP_WAIT(1); }
        else             { CP_WAIT(0); }
        __syncthreads();

        const uint32_t kB = (uint32_t)(b * ATT_K) * 2u;
        const uint32_t vB = (uint32_t)(b * ATT_V) * 2u;

        // ---- QK^T: 5 k16-blocks, 2-MMA Q-split ----
        float acc_s[8][4];
        #pragma unroll
        for (int n = 0; n < 8; n++)
            #pragma unroll
            for (int r = 0; r < 4; r++) acc_s[n][r] = 0.f;

        #pragma unroll
        for (int kk = 0; kk < 5; kk++) {
            const int kb = kk * 16;
            uint32_t ah[4], al[4];
            {
                const uint32_t off = (uint32_t)((wq + (lane & 15)) * QSTR + kb
                                                + ((lane & 16) ? 8 : 0)) * 2u;
                ldsm4(ah, uQh + off);
                ldsm4(al, uQl + off);
            }
            #pragma unroll
            for (int np = 0; np < 4; np++) {
                const uint32_t off = (uint32_t)((np * 16 + (msel >> 1) * 8 + mrow) * QSTR
                                                + kb + (msel & 1) * 8) * 2u;
                uint32_t bh4[4];
                ldsm4(bh4, uKh + kB + off);
                mma_f16(acc_s[2 * np],     ah, bh4 + 0);
                mma_f16(acc_s[2 * np],     al, bh4 + 0);
                mma_f16(acc_s[2 * np + 1], ah, bh4 + 2);
                mma_f16(acc_s[2 * np + 1], al, bh4 + 2);
            }
        }

        // ---- mask + online softmax ----
        const int k0 = start + t * 64;
        const int nv = end - k0;
        float mt0 = -INFINITY, mt1 = -INFINITY;
        #pragma unroll
        for (int nt = 0; nt < 8; nt++) {
            #pragma unroll
            for (int j = 0; j < 2; j++) {
                const int c = nt * 8 + 2 * t4 + j;
                if (c >= nv) { acc_s[nt][j] = -1e30f; acc_s[nt][2 + j] = -1e30f; }
                mt0 = fmaxf(mt0, acc_s[nt][j]);
                mt1 = fmaxf(mt1, acc_s[nt][2 + j]);
            }
        }
        mt0 = fmaxf(mt0, __shfl_xor_sync(0xffffffffu, mt0, 1));
        mt0 = fmaxf(mt0, __shfl_xor_sync(0xffffffffu, mt0, 2));
        mt1 = fmaxf(mt1, __shfl_xor_sync(0xffffffffu, mt1, 1));
        mt1 = fmaxf(mt1, __shfl_xor_sync(0xffffffffu, mt1, 2));

        const float mn0 = fmaxf(m0, mt0), mn1 = fmaxf(m1, mt1);
        const float al0 = __expf(m0 - mn0), al1 = __expf(m1 - mn1);
        m0 = mn0; m1 = mn1;

        float rs0 = 0.f, rs1 = 0.f;
        #pragma unroll
        for (int nt = 0; nt < 8; nt++) {
            #pragma unroll
            for (int j = 0; j < 2; j++) {
                const float p0 = __expf(acc_s[nt][j]     - m0);
                const float p1 = __expf(acc_s[nt][2 + j] - m1);
                acc_s[nt][j]     = p0;
                acc_s[nt][2 + j] = p1;
                rs0 += p0; rs1 += p1;
            }
        }
        rs0 += __shfl_xor_sync(0xffffffffu, rs0, 1);
        rs0 += __shfl_xor_sync(0xffffffffu, rs0, 2);
        rs1 += __shfl_xor_sync(0xffffffffu, rs1, 1);
        rs1 += __shfl_xor_sync(0xffffffffu, rs1, 2);
        l0 = l0 * al0 + rs0;
        l1 = l1 * al1 + rs1;

        #pragma unroll
        for (int n = 0; n < 10; n++) {
            acc_o[n][0] *= al0; acc_o[n][1] *= al0;
            acc_o[n][2] *= al1; acc_o[n][3] *= al1;
        }

        // ---- pack P into fp16 A-fragments ----
        uint32_t pk[4][4];
        #pragma unroll
        for (int kk = 0; kk < 4; kk++) {
            pk[kk][0] = pack_h2(acc_s[2 * kk][0],     acc_s[2 * kk][1]);
            pk[kk][1] = pack_h2(acc_s[2 * kk][2],     acc_s[2 * kk][3]);
            pk[kk][2] = pack_h2(acc_s[2 * kk + 1][0], acc_s[2 * kk + 1][1]);
            pk[kk][3] = pack_h2(acc_s[2 * kk + 1][2], acc_s[2 * kk + 1][3]);
        }

        // ---- PV: 4 k16-blocks, plain fp16 V ----
        #pragma unroll
        for (int kk = 0; kk < 4; kk++) {
            const int kb = kk * 16;
            #pragma unroll
            for (int vp = 0; vp < 5; vp++) {
                const uint32_t off = (uint32_t)((vp * 16 + (msel >> 1) * 8 + mrow) * VSTR
                                                + kb + (msel & 1) * 8) * 2u;
                uint32_t vh4[4];
                ldsm4(vh4, uVh + vB + off);
                mma_f16(acc_o[2 * vp],     pk[kk], vh4 + 0);
                mma_f16(acc_o[2 * vp + 1], pk[kk], vh4 + 2);
            }
        }
        __syncthreads();
    }

    // ---- epilogue: write fp16 ----
    const float inv0 = 1.f / l0, inv1 = 1.f / l1;
    const int r0 = q0 + wq + gid, r1 = r0 + 8;
    #pragma unroll
    for (int nt = 0; nt < 10; nt++) {
        const int col = h * HDIM + nt * 8 + 2 * t4;
        __half2 v0 = __floats2half2_rn(acc_o[nt][0] * inv0, acc_o[nt][1] * inv0);
        __half2 v1 = __floats2half2_rn(acc_o[nt][2] * inv1, acc_o[nt][3] * inv1);
        *reinterpret_cast<__half2*>(&outh[(size_t)r0 * D_MODEL + col]) = v0;
        *reinterpret_cast<__half2*>(&outh[(size_t)r1 * D_MODEL + col]) = v1;
    }
}

// ======================= launch ============================================
extern "C" void kernel_launch(void* const* d_in, const int* in_sizes, int n_in,
                              void* d_out, int out_size)
{
    const float* hidden = (const float*)d_in[0];
    const int*   cu     = (const int*)  d_in[1];
    const float* rope   = (const float*)d_in[2];
    const float* w_qkv  = (const float*)d_in[3];
    const float* b_qkv  = (const float*)d_in[4];
    const float* w_proj = (const float*)d_in[5];
    const float* b_proj = (const float*)d_in[6];
    float* out = (float*)d_out;

    const int S     = in_sizes[0] / D_MODEL;
    const int n_seg = in_sizes[1] - 1;

    float *qkv_p;
    __half *hh, *attnh, *wqh, *wph, *qh, *ql, *kh, *vh;
    cudaGetSymbolAddress((void**)&qkv_p, g_qkv);
    cudaGetSymbolAddress((void**)&hh,    g_hh);
    cudaGetSymbolAddress((void**)&attnh, g_attnh);
    cudaGetSymbolAddress((void**)&wqh,   g_wqkv_h);
    cudaGetSymbolAddress((void**)&wph,   g_wproj_h);
    cudaGetSymbolAddress((void**)&qh, g_qh);
    cudaGetSymbolAddress((void**)&ql, g_ql);
    cudaGetSymbolAddress((void**)&kh, g_kh);
    cudaGetSymbolAddress((void**)&vh, g_vh);

    cudaFuncSetAttribute(gemm_f16, cudaFuncAttributeMaxDynamicSharedMemorySize, GEMM_SMEM);
    cudaFuncSetAttribute(attn_tc,  cudaFuncAttributeMaxDynamicSharedMemorySize, ATC_SMEM);

    // 0) weight transpose -> fp16; hidden -> fp16
    {
        dim3 blk(32, 8);
        wtrans16<<<dim3(3 * D_MODEL / 32, D_MODEL / 32), blk>>>(w_qkv, wqh, D_MODEL, 3 * D_MODEL);
        wtrans16<<<dim3(D_MODEL / 32, D_MODEL / 32), blk>>>(w_proj, wph, D_MODEL, D_MODEL);
        f2h<<<(S * D_MODEL) / (256 * 4), 256>>>(hidden, hh);
    }

    // 1) QKV projection (plain fp16, BK=64)
    gemm_f16<<<dim3(3 * D_MODEL / 128, S / 128), 256, GEMM_SMEM>>>(
        hh, wqh, b_qkv, qkv_p, S, 3 * D_MODEL, D_MODEL);

    // 2) RoPE split scatter (Q hi/lo, K hi); V transpose (hi only)
    rope_scatter<<<S, 256>>>(qkv_p, rope, qh, ql, kh, S);
    vtrans<<<dim3(S / 64, NHEADS), 256>>>(qkv_p, vh, S);

    // 3) block-diagonal attention (Q-split QK, plain-V PV)
    attn_tc<<<dim3(S / 256, NHEADS), 512, ATC_SMEM>>>(
        qh, ql, kh, vh, cu, n_seg, attnh, S);

    // 4) output projection (plain fp16, BK=64)
    gemm_f16<<<dim3(D_MODEL / 128, S / 128), 256, GEMM_SMEM>>>(
        attnh, wph, b_proj, out, S, D_MODEL, D_MODEL);
}

// round 16
// speedup vs baseline: 1.4460x; 1.0474x over previous
#include <cuda_runtime.h>
#include <cuda_fp16.h>
#include <math.h>
#include <cstdint>

#define D_MODEL 1280
#define NHEADS  16
#define HDIM    80
#define S_MAX   4096

// ---------------- scratch (device globals; no allocation allowed) ----------
__device__ float  g_qkv[S_MAX * 3 * D_MODEL];
__device__ __half g_hh[S_MAX * D_MODEL];                 // hidden fp16
__device__ __half g_attnh[S_MAX * D_MODEL];              // attn out fp16
__device__ __half g_wqkv_h[3 * D_MODEL * D_MODEL];       // (3D, D) K-major fp16
__device__ __half g_wproj_h[D_MODEL * D_MODEL];
// fp16 attention tensors (all plain fp16)
__device__ __half g_qh[NHEADS * S_MAX * HDIM];           // (H,S,80) scaled
__device__ __half g_kh[NHEADS * S_MAX * HDIM];
__device__ __half g_vh[NHEADS * HDIM * S_MAX];           // (H,80,S) transposed

// ======================= helpers ===========================================
__device__ __forceinline__ uint32_t smem_u32(const void* p) {
    uint32_t a;
    asm("{ .reg .u64 t; cvta.to.shared.u64 t, %1; cvt.u32.u64 %0, t; }" : "=r"(a) : "l"(p));
    return a;
}
__device__ __forceinline__ void cp16(uint32_t dst, const void* src) {
    asm volatile("cp.async.cg.shared.global [%0], [%1], 16;" :: "r"(dst), "l"(src));
}
#define CP_COMMIT() asm volatile("cp.async.commit_group;" ::: "memory")
#define CP_WAIT(n)  asm volatile("cp.async.wait_group %0;" :: "n"(n) : "memory")

__device__ __forceinline__ void mma_f16(float* c, const uint32_t* a, const uint32_t* b) {
    asm volatile(
        "mma.sync.aligned.m16n8k16.row.col.f32.f16.f16.f32 "
        "{%0,%1,%2,%3}, {%4,%5,%6,%7}, {%8,%9}, {%0,%1,%2,%3};"
        : "+f"(c[0]), "+f"(c[1]), "+f"(c[2]), "+f"(c[3])
        : "r"(a[0]), "r"(a[1]), "r"(a[2]), "r"(a[3]), "r"(b[0]), "r"(b[1]));
}
__device__ __forceinline__ void ldsm4(uint32_t* r, uint32_t addr) {
    asm volatile("ldmatrix.sync.aligned.m8n8.x4.shared.b16 {%0,%1,%2,%3}, [%4];"
        : "=r"(r[0]), "=r"(r[1]), "=r"(r[2]), "=r"(r[3]) : "r"(addr));
}
__device__ __forceinline__ uint32_t pack_h2(float lo, float hi) {
    __half2 h = __floats2half2_rn(lo, hi);
    return *reinterpret_cast<uint32_t*>(&h);
}

// ======================= weight transpose -> fp16 ==========================
__global__ void wtrans16(const float* __restrict__ in, __half* __restrict__ oh,
                         int K, int N) {
    __shared__ float tile[32][33];
    const int k0 = blockIdx.y * 32, n0 = blockIdx.x * 32;
    const int tx = threadIdx.x, ty = threadIdx.y;
    #pragma unroll
    for (int i = ty; i < 32; i += 8)
        tile[i][tx] = in[(size_t)(k0 + i) * N + n0 + tx];
    __syncthreads();
    #pragma unroll
    for (int i = ty; i < 32; i += 8)
        oh[(size_t)(n0 + i) * K + k0 + tx] = __float2half_rn(tile[tx][i]);
}

// ======================= fp32 -> fp16 convert ==============================
__global__ void f2h(const float* __restrict__ in, __half* __restrict__ out) {
    const int i = (blockIdx.x * blockDim.x + threadIdx.x) * 4;
    float4 v = *reinterpret_cast<const float4*>(in + i);
    __half2 a = __floats2half2_rn(v.x, v.y);
    __half2 b = __floats2half2_rn(v.z, v.w);
    uint2 pk;
    pk.x = *reinterpret_cast<uint32_t*>(&a);
    pk.y = *reinterpret_cast<uint32_t*>(&b);
    *reinterpret_cast<uint2*>(out + i) = pk;
}

// ======================= plain fp16 GEMM (128x128, BK=64, 2-stage) =========
#define ASTR 72                              // 64 data + 8 pad halves
#define GEMM_STAGE (2 * 128 * ASTR)          // 18432 halves = 36864 B
#define GEMM_SMEM  73728

__global__ __launch_bounds__(256)
void gemm_f16(const __half* __restrict__ A, const __half* __restrict__ B,
              const float* __restrict__ bias, float* __restrict__ C,
              int M, int N, int K)
{
    extern __shared__ __half smh[];
    const int tid  = threadIdx.x;
    const int warp = tid >> 5, lane = tid & 31;
    const int gid  = lane >> 2, t4 = lane & 3;
    const int mrow = lane & 7, msel = lane >> 3;
    const int wm0  = (warp & 3) * 32;
    const int wn0  = (warp >> 2) * 64;
    const int bx = blockIdx.x, by = blockIdx.y;

    const __half* Ab = A + (size_t)by * 128 * K;
    const __half* Bb = B + (size_t)bx * 128 * K;
    const int NS = K / 64;
    const uint32_t sb = smem_u32(smh);

    auto load_stage = [&](int s, int ks) {
        #pragma unroll
        for (int i = 0; i < 8; i++) {
            const int id  = tid + i * 256;
            const int isB = id >= 1024;
            const int id2 = isB ? id - 1024 : id;
            const int row = id2 >> 3;
            const int c8  = (id2 & 7) * 8;
            const __half* src = (isB ? Bb : Ab) + (size_t)row * K + ks * 64 + c8;
            const uint32_t dst = sb +
                (uint32_t)(s * GEMM_STAGE + isB * 128 * ASTR + row * ASTR + c8) * 2u;
            cp16(dst, src);
        }
        CP_COMMIT();
    };

    float acc[2][8][4];
    #pragma unroll
    for (int mt = 0; mt < 2; mt++)
        #pragma unroll
        for (int nt = 0; nt < 8; nt++)
            #pragma unroll
            for (int r = 0; r < 4; r++) acc[mt][nt][r] = 0.f;

    load_stage(0, 0);
    for (int ks = 0; ks < NS; ks++) {
        const int s = ks & 1;
        if (ks + 1 < NS) { load_stage(1 - s, ks + 1); CP_WAIT(1); }
        else             { CP_WAIT(0); }
        __syncthreads();

        const uint32_t uA = sb + (uint32_t)(s * GEMM_STAGE) * 2u;
        const uint32_t uB = uA + (uint32_t)(128 * ASTR) * 2u;

        #pragma unroll
        for (int kk = 0; kk < 4; kk++) {
            const int kb = kk * 16;
            uint32_t a0[4], a1[4];
            const uint32_t aoff = (uint32_t)((wm0 + (lane & 15)) * ASTR + kb
                                             + ((lane & 16) ? 8 : 0)) * 2u;
            ldsm4(a0, uA + aoff);
            ldsm4(a1, uA + aoff + (uint32_t)(16 * ASTR) * 2u);
            #pragma unroll
            for (int np = 0; np < 4; np++) {
                const uint32_t boff = (uint32_t)((wn0 + np * 16 + (msel >> 1) * 8 + mrow) * ASTR
                                                 + kb + (msel & 1) * 8) * 2u;
                uint32_t b4[4];
                ldsm4(b4, uB + boff);
                mma_f16(acc[0][2 * np],     a0, b4 + 0);
                mma_f16(acc[0][2 * np + 1], a0, b4 + 2);
                mma_f16(acc[1][2 * np],     a1, b4 + 0);
                mma_f16(acc[1][2 * np + 1], a1, b4 + 2);
            }
        }
        __syncthreads();
    }

    float* Cs = reinterpret_cast<float*>(smh);
    #pragma unroll
    for (int mt = 0; mt < 2; mt++)
        #pragma unroll
        for (int nt = 0; nt < 8; nt++) {
            const int row = wm0 + mt * 16 + gid;
            const int col = wn0 + nt * 8 + t4 * 2;
            Cs[row * 132 + col]           = acc[mt][nt][0];
            Cs[row * 132 + col + 1]       = acc[mt][nt][1];
            Cs[(row + 8) * 132 + col]     = acc[mt][nt][2];
            Cs[(row + 8) * 132 + col + 1] = acc[mt][nt][3];
        }
    __syncthreads();
    #pragma unroll
    for (int it = 0; it < 16; it++) {
        const int id  = tid + it * 256;
        const int row = id >> 5;
        const int c4  = (id & 31) * 4;
        float4 v = *reinterpret_cast<const float4*>(&Cs[row * 132 + c4]);
        const int gc = bx * 128 + c4;
        v.x += bias[gc + 0]; v.y += bias[gc + 1]; v.z += bias[gc + 2]; v.w += bias[gc + 3];
        *reinterpret_cast<float4*>(&C[(size_t)(by * 128 + row) * N + gc]) = v;
    }
}

// ======================= RoPE + scatter (plain fp16 Q/K) ===================
__global__ void rope_scatter(const float* __restrict__ qkv,
                             const float* __restrict__ freqs,
                             __half* __restrict__ Qh,
                             __half* __restrict__ Kh,
                             int S)
{
    const int s = blockIdx.x;
    const float* base = qkv + (size_t)s * (3 * D_MODEL);
    const float scale = 0.11180339887498949f;   // 1/sqrt(80)
    for (int idx = threadIdx.x; idx < NHEADS * HDIM; idx += blockDim.x) {
        const int h = idx / HDIM;
        const int d = idx % HDIM;
        const int dd = (d < 40) ? d : d - 40;
        const float f  = freqs[(size_t)s * 40 + dd];
        const float cs = cosf(f), sn = sinf(f);
        const float q1 = base[h * HDIM + dd];
        const float q2 = base[h * HDIM + dd + 40];
        const float k1 = base[D_MODEL + h * HDIM + dd];
        const float k2 = base[D_MODEL + h * HDIM + dd + 40];
        float qo = (d < 40) ? (q1 * cs - q2 * sn) : (q1 * sn + q2 * cs);
        const float ko = (d < 40) ? (k1 * cs - k2 * sn) : (k1 * sn + k2 * cs);
        qo *= scale;
        const size_t o = ((size_t)h * S + s) * HDIM + d;
        Qh[o] = __float2half_rn(qo);
        Kh[o] = __float2half_rn(ko);
    }
}

// ======================= V transpose (fp16) ================================
__global__ void vtrans(const float* __restrict__ qkv,
                       __half* __restrict__ Vh, int S)
{
    __shared__ float tile[64][84];
    const int tid = threadIdx.x;
    const int h  = blockIdx.y;
    const int s0 = blockIdx.x * 64;
    {
        const int sl = tid >> 2;
        const int dc = (tid & 3) * 20;
        const float* src = qkv + (size_t)(s0 + sl) * (3 * D_MODEL) + 2 * D_MODEL + h * HDIM + dc;
        #pragma unroll
        for (int i = 0; i < 5; i++) {
            float4 v = *reinterpret_cast<const float4*>(src + i * 4);
            tile[sl][dc + i * 4 + 0] = v.x;
            tile[sl][dc + i * 4 + 1] = v.y;
            tile[sl][dc + i * 4 + 2] = v.z;
            tile[sl][dc + i * 4 + 3] = v.w;
        }
    }
    __syncthreads();
    if (tid < 160) {
        const int d  = tid >> 1;
        const int sh = (tid & 1) * 32;
        const size_t o = ((size_t)(h * HDIM + d)) * S + s0 + sh;
        #pragma unroll
        for (int j = 0; j < 16; j++) {
            __half2 hv = __floats2half2_rn(tile[sh + 2 * j][d], tile[sh + 2 * j + 1][d]);
            *reinterpret_cast<__half2*>(&Vh[o + 2 * j]) = hv;
        }
    }
}

// ======================= fp16 tensor-core attention ========================
// CTA = (q-tile 256, head), 16 warps x 16 q-rows, KV tile 64, 2-stage cp.async.
// QK^T: plain fp16 (1 MMA). PV: plain fp16 (1 MMA).
#define QSTR 88
#define VSTR 72
#define ATT_Q  (256 * QSTR)
#define ATT_K  (64 * QSTR)
#define ATT_V  (80 * VSTR)
#define ATC_SMEM ((ATT_Q + 2 * ATT_K + 2 * ATT_V) * 2)   // 90624 B

__global__ __launch_bounds__(512)
void attn_tc(const __half* __restrict__ gQh,
             const __half* __restrict__ gKh,
             const __half* __restrict__ gVh,
             const int* __restrict__ cu, int n_seg,
             __half* __restrict__ outh, int S)
{
    extern __shared__ __half sh[];
    __half* Qh = sh;
    __half* Kh = Qh + ATT_Q;           // [2][ATT_K]
    __half* Vh = Kh + 2 * ATT_K;       // [2][ATT_V]

    const uint32_t uQh = smem_u32(Qh);
    const uint32_t uKh = smem_u32(Kh);
    const uint32_t uVh = smem_u32(Vh);

    const int tid  = threadIdx.x;
    const int warp = tid >> 5, lane = tid & 31;
    const int gid  = lane >> 2, t4 = lane & 3;
    const int mrow = lane & 7, msel = lane >> 3;
    const int wq   = warp * 16;
    const int h    = blockIdx.y;
    const int q0   = blockIdx.x * 256;

    int start = 0, end = S;
    for (int i = 0; i < n_seg; i++) {
        int a = cu[i], b = cu[i + 1];
        if (a <= q0 && q0 < b) { start = a; end = b; }
    }

    // ---- Q load (cp.async): 2560 chunks, 5 per thread ----
    #pragma unroll
    for (int i = 0; i < 5; i++) {
        const int id  = tid + i * 512;        // 0..2559
        const int r   = id / 10;
        const int c8  = (id % 10) * 8;
        const size_t so = ((size_t)h * S + q0 + r) * HDIM + c8;
        const uint32_t dst = uQh + (uint32_t)(r * QSTR + c8) * 2u;
        cp16(dst, gQh + so);
    }

    const int nkt = (end - start + 63) / 64;

    // KV loader: K hi (640 chunks) + V hi (640 chunks) = 1280
    auto load_kv = [&](int st, int t) {
        const int k0 = start + t * 64;
        #pragma unroll
        for (int i = 0; i < 3; i++) {
            const int id = tid + i * 512;     // 0..1535
            if (id < 640) {                   // K hi
                const int r   = id / 10;
                const int c8  = (id % 10) * 8;
                const size_t so = ((size_t)h * S + k0 + r) * HDIM + c8;
                const uint32_t dst = uKh +
                    (uint32_t)(st * ATT_K + r * QSTR + c8) * 2u;
                cp16(dst, gKh + so);
            } else if (id < 1280) {           // V hi
                const int idv = id - 640;
                const int r   = idv >> 3;
                const int c8  = (idv & 7) * 8;
                const size_t so = ((size_t)(h * HDIM + r)) * S + k0 + c8;
                const uint32_t dst = uVh +
                    (uint32_t)(st * ATT_V + r * VSTR + c8) * 2u;
                cp16(dst, gVh + so);
            }
        }
        CP_COMMIT();
    };

    load_kv(0, 0);

    float acc_o[10][4];
    #pragma unroll
    for (int n = 0; n < 10; n++)
        #pragma unroll
        for (int r = 0; r < 4; r++) acc_o[n][r] = 0.f;
    float m0 = -INFINITY, m1 = -INFINITY, l0 = 0.f, l1 = 0.f;

    for (int t = 0; t < nkt; t++) {
        const int b = t & 1;
        if (t + 1 < nkt) { load_kv(1 - b, t + 1); CP_WAIT(1); }
        else             { CP_WAIT(0); }
        __syncthreads();

        const uint32_t kB = (uint32_t)(b * ATT_K) * 2u;
        const uint32_t vB = (uint32_t)(b * ATT_V) * 2u;

        // ---- QK^T: 5 k16-blocks, plain fp16 ----
        float acc_s[8][4];
        #pragma unroll
        for (int n = 0; n < 8; n++)
            #pragma unroll
            for (int r = 0; r < 4; r++) acc_s[n][r] = 0.f;

        #pragma unroll
        for (int kk = 0; kk < 5; kk++) {
            const int kb = kk * 16;
            uint32_t ah[4];
            {
                const uint32_t off = (uint32_t)((wq + (lane & 15)) * QSTR + kb
                                                + ((lane & 16) ? 8 : 0)) * 2u;
                ldsm4(ah, uQh + off);
            }
            #pragma unroll
            for (int np = 0; np < 4; np++) {
                const uint32_t off = (uint32_t)((np * 16 + (msel >> 1) * 8 + mrow) * QSTR
                                                + kb + (msel & 1) * 8) * 2u;
                uint32_t bh4[4];
                ldsm4(bh4, uKh + kB + off);
                mma_f16(acc_s[2 * np],     ah, bh4 + 0);
                mma_f16(acc_s[2 * np + 1], ah, bh4 + 2);
            }
        }

        // ---- mask + online softmax ----
        const int k0 = start + t * 64;
        const int nv = end - k0;
        float mt0 = -INFINITY, mt1 = -INFINITY;
        #pragma unroll
        for (int nt = 0; nt < 8; nt++) {
            #pragma unroll
            for (int j = 0; j < 2; j++) {
                const int c = nt * 8 + 2 * t4 + j;
                if (c >= nv) { acc_s[nt][j] = -1e30f; acc_s[nt][2 + j] = -1e30f; }
                mt0 = fmaxf(mt0, acc_s[nt][j]);
                mt1 = fmaxf(mt1, acc_s[nt][2 + j]);
            }
        }
        mt0 = fmaxf(mt0, __shfl_xor_sync(0xffffffffu, mt0, 1));
        mt0 = fmaxf(mt0, __shfl_xor_sync(0xffffffffu, mt0, 2));
        mt1 = fmaxf(mt1, __shfl_xor_sync(0xffffffffu, mt1, 1));
        mt1 = fmaxf(mt1, __shfl_xor_sync(0xffffffffu, mt1, 2));

        const float mn0 = fmaxf(m0, mt0), mn1 = fmaxf(m1, mt1);
        const float al0 = __expf(m0 - mn0), al1 = __expf(m1 - mn1);
        m0 = mn0; m1 = mn1;

        float rs0 = 0.f, rs1 = 0.f;
        #pragma unroll
        for (int nt = 0; nt < 8; nt++) {
            #pragma unroll
            for (int j = 0; j < 2; j++) {
                const float p0 = __expf(acc_s[nt][j]     - m0);
                const float p1 = __expf(acc_s[nt][2 + j] - m1);
                acc_s[nt][j]     = p0;
                acc_s[nt][2 + j] = p1;
                rs0 += p0; rs1 += p1;
            }
        }
        rs0 += __shfl_xor_sync(0xffffffffu, rs0, 1);
        rs0 += __shfl_xor_sync(0xffffffffu, rs0, 2);
        rs1 += __shfl_xor_sync(0xffffffffu, rs1, 1);
        rs1 += __shfl_xor_sync(0xffffffffu, rs1, 2);
        l0 = l0 * al0 + rs0;
        l1 = l1 * al1 + rs1;

        #pragma unroll
        for (int n = 0; n < 10; n++) {
            acc_o[n][0] *= al0; acc_o[n][1] *= al0;
            acc_o[n][2] *= al1; acc_o[n][3] *= al1;
        }

        // ---- pack P into fp16 A-fragments ----
        uint32_t pk[4][4];
        #pragma unroll
        for (int kk = 0; kk < 4; kk++) {
            pk[kk][0] = pack_h2(acc_s[2 * kk][0],     acc_s[2 * kk][1]);
            pk[kk][1] = pack_h2(acc_s[2 * kk][2],     acc_s[2 * kk][3]);
            pk[kk][2] = pack_h2(acc_s[2 * kk + 1][0], acc_s[2 * kk + 1][1]);
            pk[kk][3] = pack_h2(acc_s[2 * kk + 1][2], acc_s[2 * kk + 1][3]);
        }

        // ---- PV: 4 k16-blocks, plain fp16 V ----
        #pragma unroll
        for (int kk = 0; kk < 4; kk++) {
            const int kb = kk * 16;
            #pragma unroll
            for (int vp = 0; vp < 5; vp++) {
                const uint32_t off = (uint32_t)((vp * 16 + (msel >> 1) * 8 + mrow) * VSTR
                                                + kb + (msel & 1) * 8) * 2u;
                uint32_t vh4[4];
                ldsm4(vh4, uVh + vB + off);
                mma_f16(acc_o[2 * vp],     pk[kk], vh4 + 0);
                mma_f16(acc_o[2 * vp + 1], pk[kk], vh4 + 2);
            }
        }
        __syncthreads();
    }

    // ---- epilogue: write fp16 ----
    const float inv0 = 1.f / l0, inv1 = 1.f / l1;
    const int r0 = q0 + wq + gid, r1 = r0 + 8;
    #pragma unroll
    for (int nt = 0; nt < 10; nt++) {
        const int col = h * HDIM + nt * 8 + 2 * t4;
        __half2 v0 = __floats2half2_rn(acc_o[nt][0] * inv0, acc_o[nt][1] * inv0);
        __half2 v1 = __floats2half2_rn(acc_o[nt][2] * inv1, acc_o[nt][3] * inv1);
        *reinterpret_cast<__half2*>(&outh[(size_t)r0 * D_MODEL + col]) = v0;
        *reinterpret_cast<__half2*>(&outh[(size_t)r1 * D_MODEL + col]) = v1;
    }
}

// ======================= launch ============================================
extern "C" void kernel_launch(void* const* d_in, const int* in_sizes, int n_in,
                              void* d_out, int out_size)
{
    const float* hidden = (const float*)d_in[0];
    const int*   cu     = (const int*)  d_in[1];
    const float* rope   = (const float*)d_in[2];
    const float* w_qkv  = (const float*)d_in[3];
    const float* b_qkv  = (const float*)d_in[4];
    const float* w_proj = (const float*)d_in[5];
    const float* b_proj = (const float*)d_in[6];
    float* out = (float*)d_out;

    const int S     = in_sizes[0] / D_MODEL;
    const int n_seg = in_sizes[1] - 1;

    float *qkv_p;
    __half *hh, *attnh, *wqh, *wph, *qh, *kh, *vh;
    cudaGetSymbolAddress((void**)&qkv_p, g_qkv);
    cudaGetSymbolAddress((void**)&hh,    g_hh);
    cudaGetSymbolAddress((void**)&attnh, g_attnh);
    cudaGetSymbolAddress((void**)&wqh,   g_wqkv_h);
    cudaGetSymbolAddress((void**)&wph,   g_wproj_h);
    cudaGetSymbolAddress((void**)&qh, g_qh);
    cudaGetSymbolAddress((void**)&kh, g_kh);
    cudaGetSymbolAddress((void**)&vh, g_vh);

    cudaFuncSetAttribute(gemm_f16, cudaFuncAttributeMaxDynamicSharedMemorySize, GEMM_SMEM);
    cudaFuncSetAttribute(attn_tc,  cudaFuncAttributeMaxDynamicSharedMemorySize, ATC_SMEM);

    // 0) weight transpose -> fp16; hidden -> fp16
    {
        dim3 blk(32, 8);
        wtrans16<<<dim3(3 * D_MODEL / 32, D_MODEL / 32), blk>>>(w_qkv, wqh, D_MODEL, 3 * D_MODEL);
        wtrans16<<<dim3(D_MODEL / 32, D_MODEL / 32), blk>>>(w_proj, wph, D_MODEL, D_MODEL);
        f2h<<<(S * D_MODEL) / (256 * 4), 256>>>(hidden, hh);
    }

    // 1) QKV projection (plain fp16, BK=64)
    gemm_f16<<<dim3(3 * D_MODEL / 128, S / 128), 256, GEMM_SMEM>>>(
        hh, wqh, b_qkv, qkv_p, S, 3 * D_MODEL, D_MODEL);

    // 2) RoPE scatter (plain fp16 Q/K); V transpose
    rope_scatter<<<S, 256>>>(qkv_p, rope, qh, kh, S);
    vtrans<<<dim3(S / 64, NHEADS), 256>>>(qkv_p, vh, S);

    // 3) block-diagonal attention (all plain fp16)
    attn_tc<<<dim3(S / 256, NHEADS), 512, ATC_SMEM>>>(
        qh, kh, vh, cu, n_seg, attnh, S);

    // 4) output projection (plain fp16, BK=64)
    gemm_f16<<<dim3(D_MODEL / 128, S / 128), 256, GEMM_SMEM>>>(
        attnh, wph, b_proj, out, S, D_MODEL, D_MODEL);
}